// round 9
// baseline (speedup 1.0000x reference)
#include <cuda_runtime.h>
#include <cuda_bf16.h>
#include <cstdint>

// ---------------------------------------------------------------------------
// ScaleSelfAttention: out = x + gamma * softmax((xWf)(xWg)^T) (xWh)
// B=4, N=4096, C=256, d=32
//  proj_kernel: h bf16 transposed [b][c][tok]; f,g bf16 hi/lo split stored
//               64-wide [hi(32)|lo(32)]; ||f||^2; per-block max ||g||^2;
//               resets the attn work counter.
//  attn_kernel: persistent CTAs (444 = 148*3), dynamic work counter over
//               512 tiles of 32 queries. S = 3-term bf16 split MMA
//               (hi.hi + hi.lo + lo.hi); P = exp(S - mhat),
//               mhat = ||f||*max||g|| (upper bound -> single pass);
//               O += P.H via mma.sync bf16, acc 32 fp32/thread -> 3 CTAs/SM.
// ---------------------------------------------------------------------------

#define BATCH 4
#define NTOK  4096
#define CDIM  256
#define DDIM  32
#define NWORK 512               // 4 batches x 128 q-tiles of 32

__device__ __nv_bfloat16 g_fe[BATCH * NTOK * 64];   // [tok][hi32|lo32]
__device__ __nv_bfloat16 g_ge[BATCH * NTOK * 64];
__device__ __nv_bfloat16 g_ht[BATCH * CDIM * NTOK];
__device__ float         g_fn2[BATCH * NTOK];
__device__ float         g_g2blk[256];
__device__ int           g_ctr;

typedef unsigned long long ull;

__device__ __forceinline__ void fma2(ull& d, ull a, ull b) {
    asm("fma.rn.f32x2 %0, %1, %2, %0;" : "+l"(d) : "l"(a), "l"(b));
}
__device__ __forceinline__ ull splat2(float v) {
    ull r;
    asm("mov.b64 %0, {%1, %1};" : "=l"(r) : "f"(v));
    return r;
}
__device__ __forceinline__ float2 unpack2(ull v) {
    float2 r;
    asm("mov.b64 {%0, %1}, %2;" : "=f"(r.x), "=f"(r.y) : "l"(v));
    return r;
}
__device__ __forceinline__ uint32_t pack_bf2(float a, float b) {
    __nv_bfloat162 v = __floats2bfloat162_rn(a, b);
    return *(uint32_t*)&v;
}

// ---------------------------------------------------------------------------
// Projections
// ---------------------------------------------------------------------------
__global__ __launch_bounds__(256) void proj_kernel(
    const float* __restrict__ x,
    const float* __restrict__ wf,
    const float* __restrict__ wg,
    const float* __restrict__ wh)
{
    __shared__ float sX[64 * 65];
    __shared__ float sW[64 * 64];
    __shared__ float sGm[2];

    const int t = threadIdx.x;
    const int rowBase = blockIdx.x * 64;
    const int bb = rowBase >> 12;
    const int tokBase = rowBase & 4095;
    const int rg = t >> 4;
    const int cg = t & 15;

    if (blockIdx.x == 0 && t == 0) g_ctr = 0;

    ull acc[5][8];
#pragma unroll
    for (int cc = 0; cc < 5; cc++)
#pragma unroll
        for (int q = 0; q < 8; q++) acc[cc][q] = 0ull;

    for (int kc = 0; kc < 4; kc++) {
        __syncthreads();
        for (int idx = t; idx < 4096; idx += 256) {
            int r = idx >> 6, kk = idx & 63;
            sX[r * 65 + kk] = x[(rowBase + r) * 256 + kc * 64 + kk];
        }
#pragma unroll
        for (int cc = 0; cc < 5; cc++) {
            __syncthreads();
            for (int idx = t; idx < 4096; idx += 256) {
                int kk = idx >> 6, j = idx & 63;
                int kglob = kc * 64 + kk;
                int c = cc * 64 + j;
                float w;
                if (c < 32)       w = wf[kglob * 32 + c];
                else if (c < 64)  w = wg[kglob * 32 + (c - 32)];
                else              w = wh[kglob * 256 + (c - 64)];
                sW[kk * 64 + j] = w;
            }
            __syncthreads();
#pragma unroll 4
            for (int kk = 0; kk < 64; kk++) {
                ulonglong2 bp = *(const ulonglong2*)&sW[kk * 64 + cg * 4];
                ull as[4];
#pragma unroll
                for (int i = 0; i < 4; i++)
                    as[i] = splat2(sX[(rg * 4 + i) * 65 + kk]);
#pragma unroll
                for (int i = 0; i < 4; i++) {
                    fma2(acc[cc][i * 2 + 0], as[i], bp.x);
                    fma2(acc[cc][i * 2 + 1], as[i], bp.y);
                }
            }
        }
    }

#pragma unroll
    for (int cc = 0; cc < 5; cc++) {
        __syncthreads();
#pragma unroll
        for (int i = 0; i < 4; i++) {
            float2 lo = unpack2(acc[cc][i * 2 + 0]);
            float2 hi = unpack2(acc[cc][i * 2 + 1]);
            sX[(rg * 4 + i) * 65 + cg * 4 + 0] = lo.x;
            sX[(rg * 4 + i) * 65 + cg * 4 + 1] = lo.y;
            sX[(rg * 4 + i) * 65 + cg * 4 + 2] = hi.x;
            sX[(rg * 4 + i) * 65 + cg * 4 + 3] = hi.y;
        }
        __syncthreads();

        if (cc == 0) {
            float g2 = 0.f;
            if (t < 64) {
                float f2 = 0.f;
#pragma unroll 8
                for (int k = 0; k < 32; k++) {
                    float v = sX[t * 65 + k];      f2 += v * v;
                    float w = sX[t * 65 + 32 + k]; g2 += w * w;
                }
                g_fn2[rowBase + t] = f2;
#pragma unroll
                for (int o = 16; o > 0; o >>= 1)
                    g2 = fmaxf(g2, __shfl_xor_sync(0xffffffffu, g2, o));
                if ((t & 31) == 0) sGm[t >> 5] = g2;
            }
            // hi/lo split operands, 64 wide: [hi(32) | lo(32)]
            for (int idx = t; idx < 64 * 32; idx += 256) {
                int tok = idx >> 5;
                int c0 = (idx & 31) * 2;
                int j = c0 & 31;
                size_t grow = (size_t)(bb * 4096 + tokBase + tok) * 64 + c0;
                {
                    float f0 = sX[tok * 65 + j];
                    float f1 = sX[tok * 65 + j + 1];
                    __nv_bfloat16 h0 = __float2bfloat16(f0);
                    __nv_bfloat16 h1 = __float2bfloat16(f1);
                    uint32_t w;
                    if (c0 < 32) { __nv_bfloat162 v2 = {h0, h1}; w = *(uint32_t*)&v2; }
                    else w = pack_bf2(f0 - __bfloat162float(h0),
                                      f1 - __bfloat162float(h1));
                    *(uint32_t*)&g_fe[grow] = w;
                }
                {
                    float ga = sX[tok * 65 + 32 + j];
                    float gb = sX[tok * 65 + 32 + j + 1];
                    __nv_bfloat16 h0 = __float2bfloat16(ga);
                    __nv_bfloat16 h1 = __float2bfloat16(gb);
                    uint32_t w;
                    if (c0 < 32) { __nv_bfloat162 v2 = {h0, h1}; w = *(uint32_t*)&v2; }
                    else w = pack_bf2(ga - __bfloat162float(h0),
                                      gb - __bfloat162float(h1));
                    *(uint32_t*)&g_ge[grow] = w;
                }
            }
        } else {
            for (int idx = t; idx < 4096; idx += 256) {
                int c = idx >> 6, tok = idx & 63;
                float v = sX[tok * 65 + c];
                g_ht[(size_t)(bb * 256 + (cc - 1) * 64 + c) * 4096 + tokBase + tok] =
                    __float2bfloat16(v);
            }
        }
    }
    __syncthreads();
    if (t == 0) g_g2blk[blockIdx.x] = fmaxf(sGm[0], sGm[1]);
}

// ---------------------------------------------------------------------------
// Attention kernel: persistent, 32 q/tile, 3 CTAs/SM target
// ---------------------------------------------------------------------------
#define HS_STRIDE 144
#define PB_STRIDE 144
#define FE_STRIDE 144
#define HS_OFF 0                      // 256*144 = 36864
#define PB_OFF 36864                  // 32*144  = 4608
#define FE_OFF 41472                  // 32*144  = 4608
#define GE_OFF 46080                  // 2*64*144 = 18432
#define GE_BUF 9216
#define SLP_OFF 64512                 // 4*32*4 = 512
#define SR_OFF 65024                  // 32
#define SGM_OFF 65056                 // 16
#define SNX_OFF 65072                 // 4
#define SM_BYTES 65088

__device__ __forceinline__ uint32_t smem_u32(const void* p) {
    uint32_t a;
    asm("{ .reg .u64 t; cvta.to.shared.u64 t, %1; cvt.u32.u64 %0, t; }"
        : "=r"(a) : "l"(p));
    return a;
}
__device__ __forceinline__ void cp_async16(uint32_t dst, const void* src) {
    asm volatile("cp.async.cg.shared.global [%0], [%1], 16;"
                 :: "r"(dst), "l"(src) : "memory");
}
__device__ __forceinline__ void mma16816(float* d, const uint32_t* a,
                                         const uint32_t* bv) {
    asm volatile(
        "mma.sync.aligned.m16n8k16.row.col.f32.bf16.bf16.f32 "
        "{%0,%1,%2,%3}, {%4,%5,%6,%7}, {%8,%9}, {%0,%1,%2,%3};"
        : "+f"(d[0]), "+f"(d[1]), "+f"(d[2]), "+f"(d[3])
        : "r"(a[0]), "r"(a[1]), "r"(a[2]), "r"(a[3]), "r"(bv[0]), "r"(bv[1]));
}
#define LDMX4(r0, r1, r2, r3, addr) \
    asm volatile("ldmatrix.sync.aligned.m8n8.x4.shared.b16 {%0,%1,%2,%3}, [%4];" \
                 : "=r"(r0), "=r"(r1), "=r"(r2), "=r"(r3) : "r"(addr))
#define CP_COMMIT() asm volatile("cp.async.commit_group;" ::: "memory")
#define CP_WAIT0()  asm volatile("cp.async.wait_group 0;" ::: "memory")

__global__ __launch_bounds__(256, 3) void attn_kernel(
    const float* __restrict__ x,
    const float* __restrict__ gamma_p,
    float* __restrict__ out)
{
    extern __shared__ char sm[];
    const int t = threadIdx.x;
    const int lane = t & 31;
    const int wid = t >> 5;
    const int gid = lane >> 2;
    const int tig = lane & 3;
    const int qw = wid & 1;        // 16-query slab
    const int kwS = wid >> 1;      // S: 16-key slice (of 64-key tile)
    const int cslab = (wid >> 1) * 64;   // O: 64-channel quarter

    float* sLp  = (float*)(sm + SLP_OFF);
    float* sR   = (float*)(sm + SR_OFF);
    float* sGms = (float*)(sm + SGM_OFF);
    int*   sNx  = (int*)(sm + SNX_OFF);
    const uint32_t smbase = smem_u32(sm);

    const int r0 = qw * 16 + gid;
    const int r1 = r0 + 8;
    const float gamma = *gamma_p;

    // ---- once: per-batch gmax (warp w handles batch w&3) ----
    {
        float gv = fmaxf(g_g2blk[(wid & 3) * 64 + lane],
                         g_g2blk[(wid & 3) * 64 + 32 + lane]);
#pragma unroll
        for (int o = 16; o > 0; o >>= 1)
            gv = fmaxf(gv, __shfl_xor_sync(0xffffffffu, gv, o));
        if (lane == 0) sR[wid] = gv;
    }
    __syncthreads();
    if (t < 4) sGms[t] = sqrtf(fmaxf(sR[t], sR[t + 4]));
    // (visible after the first work-loop barrier)

    // lane-relative ldmatrix offsets
    const uint32_t aS_l  = (qw * 16 + (lane & 15)) * FE_STRIDE + ((lane >> 4) << 4);
    const uint32_t bS_l  = (kwS * 16 + (lane & 7)) * FE_STRIDE + ((lane >> 3) << 4);
    const uint32_t aO_l  = (qw * 16 + (lane & 15)) * PB_STRIDE + ((lane >> 4) << 4);
    const uint32_t bO_l  = (cslab + (lane & 7)) * HS_STRIDE + ((lane >> 3) << 4);

    for (;;) {
        __syncthreads();                    // prev epilogue done; smem reusable
        if (t == 0) *sNx = atomicAdd(&g_ctr, 1);
        __syncthreads();
        const int n = *sNx;
        if (n >= NWORK) break;
        const int b = n >> 7;
        const int qBase = (n & 127) * 32;

        // ---- prologue: FE + GE(0) ----
        {
            int row = t >> 3, ch = t & 7;
            cp_async16(smbase + FE_OFF + row * FE_STRIDE + ch * 16,
                       g_fe + (size_t)(b * 4096 + qBase + row) * 64 + ch * 8);
        }
#pragma unroll
        for (int it = 0; it < 2; it++) {
            int idx = t + it * 256;
            int row = idx >> 3, ch = idx & 7;
            cp_async16(smbase + GE_OFF + row * FE_STRIDE + ch * 16,
                       g_ge + (size_t)(b * 4096 + row) * 64 + ch * 8);
        }
        CP_COMMIT();

        const float gms = sGms[b];
        const float mh0 = sqrtf(g_fn2[b * 4096 + qBase + r0]) * gms;
        const float mh1 = sqrtf(g_fn2[b * 4096 + qBase + r1]) * gms;

        float acc[8][4];
#pragma unroll
        for (int nj = 0; nj < 8; nj++)
#pragma unroll
            for (int q = 0; q < 4; q++) acc[nj][q] = 0.f;
        float rsum0 = 0.f, rsum1 = 0.f;

        CP_WAIT0();
        __syncthreads();

        for (int kt = 0; kt < 64; kt++) {
            // (top of tile: O(kt-1) done via bottom barrier of prev iter)
            // cp HS(kt) [256c x 64k] + GE(kt+1)
#pragma unroll
            for (int it = 0; it < 8; it++) {
                int idx = t + it * 256;
                int ch = idx >> 3, part = idx & 7;
                cp_async16(smbase + HS_OFF + ch * HS_STRIDE + part * 16,
                           g_ht + (size_t)(b * 256 + ch) * 4096 + kt * 64 + part * 8);
            }
            if (kt < 63) {
#pragma unroll
                for (int it = 0; it < 2; it++) {
                    int idx = t + it * 256;
                    int row = idx >> 3, ch = idx & 7;
                    cp_async16(smbase + GE_OFF + ((kt + 1) & 1) * GE_BUF +
                                   row * FE_STRIDE + ch * 16,
                               g_ge + (size_t)(b * 4096 + (kt + 1) * 64 + row) * 64 + ch * 8);
                }
            }
            CP_COMMIT();

            // ---- S-MMA: m16 n16, 3 split terms ----
            const uint32_t aS = smbase + FE_OFF + aS_l;
            const uint32_t bS = smbase + GE_OFF + (kt & 1) * GE_BUF + bS_l;
            uint32_t ahi[8], alo[8], bhi[8], blo[8];
            LDMX4(ahi[0], ahi[1], ahi[2], ahi[3], aS);
            LDMX4(ahi[4], ahi[5], ahi[6], ahi[7], aS + 32);
            LDMX4(alo[0], alo[1], alo[2], alo[3], aS + 64);
            LDMX4(alo[4], alo[5], alo[6], alo[7], aS + 96);
            LDMX4(bhi[0], bhi[1], bhi[2], bhi[3], bS);            // n8 blk0, k32 hi
            LDMX4(bhi[4], bhi[5], bhi[6], bhi[7], bS + 8 * FE_STRIDE);
            LDMX4(blo[0], blo[1], blo[2], blo[3], bS + 64);
            LDMX4(blo[4], blo[5], blo[6], blo[7], bS + 8 * FE_STRIDE + 64);

            float sacc[2][4];
#pragma unroll
            for (int nb = 0; nb < 2; nb++) {
#pragma unroll
                for (int q = 0; q < 4; q++) sacc[nb][q] = 0.f;
                mma16816(sacc[nb], &ahi[0], &bhi[nb * 4]);       // hi.hi k0:16
                mma16816(sacc[nb], &ahi[4], &bhi[nb * 4 + 2]);   // hi.hi k16:32
                mma16816(sacc[nb], &ahi[0], &blo[nb * 4]);       // hi.lo
                mma16816(sacc[nb], &ahi[4], &blo[nb * 4 + 2]);
                mma16816(sacc[nb], &alo[0], &bhi[nb * 4]);       // lo.hi
                mma16816(sacc[nb], &alo[4], &bhi[nb * 4 + 2]);
            }

            // ---- P = exp(S - mhat), PB store, row sums ----
            {
                float rs0 = 0.f, rs1 = 0.f;
#pragma unroll
                for (int nb = 0; nb < 2; nb++) {
                    float p0 = __expf(sacc[nb][0] - mh0);
                    float p1 = __expf(sacc[nb][1] - mh0);
                    float p2 = __expf(sacc[nb][2] - mh1);
                    float p3 = __expf(sacc[nb][3] - mh1);
                    rs0 += p0 + p1;
                    rs1 += p2 + p3;
                    int key = kwS * 16 + nb * 8 + tig * 2;
                    *(uint32_t*)(sm + PB_OFF + r0 * PB_STRIDE + key * 2) = pack_bf2(p0, p1);
                    *(uint32_t*)(sm + PB_OFF + r1 * PB_STRIDE + key * 2) = pack_bf2(p2, p3);
                }
                rs0 += __shfl_xor_sync(0xffffffffu, rs0, 1);
                rs0 += __shfl_xor_sync(0xffffffffu, rs0, 2);
                rs1 += __shfl_xor_sync(0xffffffffu, rs1, 1);
                rs1 += __shfl_xor_sync(0xffffffffu, rs1, 2);
                rsum0 += rs0;
                rsum1 += rs1;
            }

            CP_WAIT0();
            __syncthreads();   // HS(kt), GE(kt+1), PB(kt) visible

            // ---- O-MMA: A = P[16q x 64k], B = H[64c x 64k] ----
            {
                const uint32_t aO = smbase + PB_OFF + aO_l;
                const uint32_t bO = smbase + HS_OFF + bO_l;
                uint32_t af[16];
                LDMX4(af[0],  af[1],  af[2],  af[3],  aO);
                LDMX4(af[4],  af[5],  af[6],  af[7],  aO + 32);
                LDMX4(af[8],  af[9],  af[10], af[11], aO + 64);
                LDMX4(af[12], af[13], af[14], af[15], aO + 96);
#pragma unroll
                for (int nj = 0; nj < 8; nj++) {
                    uint32_t bf[8];
                    LDMX4(bf[0], bf[1], bf[2], bf[3], bO + nj * 8 * HS_STRIDE);
                    LDMX4(bf[4], bf[5], bf[6], bf[7], bO + nj * 8 * HS_STRIDE + 64);
                    mma16816(acc[nj], &af[0],  &bf[0]);
                    mma16816(acc[nj], &af[4],  &bf[2]);
                    mma16816(acc[nj], &af[8],  &bf[4]);
                    mma16816(acc[nj], &af[12], &bf[6]);
                }
            }
            __syncthreads();   // O done before HS/PB overwritten next iter
        }

        // ---- row sums ----
        if (tig == 0) {
            sLp[kwS * 32 + r0] = rsum0;
            sLp[kwS * 32 + r1] = rsum1;
        }
        __syncthreads();

        // ---- epilogue ----
        const float gl0 = gamma / (sLp[r0] + sLp[32 + r0] + sLp[64 + r0] + sLp[96 + r0]);
        const float gl1 = gamma / (sLp[r1] + sLp[32 + r1] + sLp[64 + r1] + sLp[96 + r1]);
        const size_t gb0 = (size_t)(b * NTOK + qBase + r0) * CDIM + cslab + tig * 2;
        const size_t gb1 = (size_t)(b * NTOK + qBase + r1) * CDIM + cslab + tig * 2;
#pragma unroll
        for (int nj = 0; nj < 8; nj++) {
            float2 xv0 = *(const float2*)&x[gb0 + nj * 8];
            float2 xv1 = *(const float2*)&x[gb1 + nj * 8];
            float2 o0, o1;
            o0.x = xv0.x + gl0 * acc[nj][0];
            o0.y = xv0.y + gl0 * acc[nj][1];
            o1.x = xv1.x + gl1 * acc[nj][2];
            o1.y = xv1.y + gl1 * acc[nj][3];
            *(float2*)&out[gb0 + nj * 8] = o0;
            *(float2*)&out[gb1 + nj * 8] = o1;
        }
    }
}

// ---------------------------------------------------------------------------
extern "C" void kernel_launch(void* const* d_in, const int* in_sizes, int n_in,
                              void* d_out, int out_size)
{
    const float* x  = (const float*)d_in[0];
    const float* wf = (const float*)d_in[1];
    const float* wg = (const float*)d_in[2];
    const float* wh = (const float*)d_in[3];
    const float* gm = (const float*)d_in[4];
    float* out = (float*)d_out;

    cudaFuncSetAttribute(attn_kernel,
                         cudaFuncAttributeMaxDynamicSharedMemorySize,
                         SM_BYTES);

    proj_kernel<<<256, 256>>>(x, wf, wg, wh);
    attn_kernel<<<444, 256, SM_BYTES>>>(x, gm, out);
}

// round 10
// speedup vs baseline: 1.0027x; 1.0027x over previous
#include <cuda_runtime.h>
#include <cuda_bf16.h>
#include <cstdint>

// ---------------------------------------------------------------------------
// ScaleSelfAttention: out = x + gamma * softmax((xWf)(xWg)^T) (xWh)
// B=4, N=4096, C=256, d=32
//  proj_kernel: h bf16 transposed [b][c][tok]; f,g bf16 hi/lo split stored
//               64-wide [hi(32)|lo(32)]; ||f||^2; per-block max ||g||^2;
//               resets the attn work counter.
//  attn_kernel: persistent CTAs (444 = 148*3), dynamic work counter over
//               512 tiles of 32 queries. S = 3-term bf16 split MMA
//               (hi.hi + hi.lo + lo.hi); P = exp(S - mhat),
//               mhat = ||f||*max||g|| (upper bound -> single pass);
//               O += P.H via mma.sync bf16, acc 32 fp32/thread -> 3 CTAs/SM.
// ---------------------------------------------------------------------------

#define BATCH 4
#define NTOK  4096
#define CDIM  256
#define DDIM  32
#define NWORK 512               // 4 batches x 128 q-tiles of 32

__device__ __nv_bfloat16 g_fe[BATCH * NTOK * 64];   // [tok][hi32|lo32]
__device__ __nv_bfloat16 g_ge[BATCH * NTOK * 64];
__device__ __nv_bfloat16 g_ht[BATCH * CDIM * NTOK];
__device__ float         g_fn2[BATCH * NTOK];
__device__ float         g_g2blk[256];
__device__ int           g_ctr;

typedef unsigned long long ull;

__device__ __forceinline__ void fma2(ull& d, ull a, ull b) {
    asm("fma.rn.f32x2 %0, %1, %2, %0;" : "+l"(d) : "l"(a), "l"(b));
}
__device__ __forceinline__ ull splat2(float v) {
    ull r;
    asm("mov.b64 %0, {%1, %1};" : "=l"(r) : "f"(v));
    return r;
}
__device__ __forceinline__ float2 unpack2(ull v) {
    float2 r;
    asm("mov.b64 {%0, %1}, %2;" : "=f"(r.x), "=f"(r.y) : "l"(v));
    return r;
}
__device__ __forceinline__ uint32_t pack_bf2(float a, float b) {
    __nv_bfloat162 v = __floats2bfloat162_rn(a, b);
    return *(uint32_t*)&v;
}

// ---------------------------------------------------------------------------
// Projections
// ---------------------------------------------------------------------------
__global__ __launch_bounds__(256) void proj_kernel(
    const float* __restrict__ x,
    const float* __restrict__ wf,
    const float* __restrict__ wg,
    const float* __restrict__ wh)
{
    __shared__ float sX[64 * 65];
    __shared__ float sW[64 * 64];
    __shared__ float sGm[2];

    const int t = threadIdx.x;
    const int rowBase = blockIdx.x * 64;
    const int bb = rowBase >> 12;
    const int tokBase = rowBase & 4095;
    const int rg = t >> 4;
    const int cg = t & 15;

    if (blockIdx.x == 0 && t == 0) g_ctr = 0;

    ull acc[5][8];
#pragma unroll
    for (int cc = 0; cc < 5; cc++)
#pragma unroll
        for (int q = 0; q < 8; q++) acc[cc][q] = 0ull;

    for (int kc = 0; kc < 4; kc++) {
        __syncthreads();
        for (int idx = t; idx < 4096; idx += 256) {
            int r = idx >> 6, kk = idx & 63;
            sX[r * 65 + kk] = x[(rowBase + r) * 256 + kc * 64 + kk];
        }
#pragma unroll
        for (int cc = 0; cc < 5; cc++) {
            __syncthreads();
            for (int idx = t; idx < 4096; idx += 256) {
                int kk = idx >> 6, j = idx & 63;
                int kglob = kc * 64 + kk;
                int c = cc * 64 + j;
                float w;
                if (c < 32)       w = wf[kglob * 32 + c];
                else if (c < 64)  w = wg[kglob * 32 + (c - 32)];
                else              w = wh[kglob * 256 + (c - 64)];
                sW[kk * 64 + j] = w;
            }
            __syncthreads();
#pragma unroll 4
            for (int kk = 0; kk < 64; kk++) {
                ulonglong2 bp = *(const ulonglong2*)&sW[kk * 64 + cg * 4];
                ull as[4];
#pragma unroll
                for (int i = 0; i < 4; i++)
                    as[i] = splat2(sX[(rg * 4 + i) * 65 + kk]);
#pragma unroll
                for (int i = 0; i < 4; i++) {
                    fma2(acc[cc][i * 2 + 0], as[i], bp.x);
                    fma2(acc[cc][i * 2 + 1], as[i], bp.y);
                }
            }
        }
    }

#pragma unroll
    for (int cc = 0; cc < 5; cc++) {
        __syncthreads();
#pragma unroll
        for (int i = 0; i < 4; i++) {
            float2 lo = unpack2(acc[cc][i * 2 + 0]);
            float2 hi = unpack2(acc[cc][i * 2 + 1]);
            sX[(rg * 4 + i) * 65 + cg * 4 + 0] = lo.x;
            sX[(rg * 4 + i) * 65 + cg * 4 + 1] = lo.y;
            sX[(rg * 4 + i) * 65 + cg * 4 + 2] = hi.x;
            sX[(rg * 4 + i) * 65 + cg * 4 + 3] = hi.y;
        }
        __syncthreads();

        if (cc == 0) {
            float g2 = 0.f;
            if (t < 64) {
                float f2 = 0.f;
#pragma unroll 8
                for (int k = 0; k < 32; k++) {
                    float v = sX[t * 65 + k];      f2 += v * v;
                    float w = sX[t * 65 + 32 + k]; g2 += w * w;
                }
                g_fn2[rowBase + t] = f2;
#pragma unroll
                for (int o = 16; o > 0; o >>= 1)
                    g2 = fmaxf(g2, __shfl_xor_sync(0xffffffffu, g2, o));
                if ((t & 31) == 0) sGm[t >> 5] = g2;
            }
            // hi/lo split operands, 64 wide: [hi(32) | lo(32)]
            for (int idx = t; idx < 64 * 32; idx += 256) {
                int tok = idx >> 5;
                int c0 = (idx & 31) * 2;
                int j = c0 & 31;
                size_t grow = (size_t)(bb * 4096 + tokBase + tok) * 64 + c0;
                {
                    float f0 = sX[tok * 65 + j];
                    float f1 = sX[tok * 65 + j + 1];
                    __nv_bfloat16 h0 = __float2bfloat16(f0);
                    __nv_bfloat16 h1 = __float2bfloat16(f1);
                    uint32_t w;
                    if (c0 < 32) { __nv_bfloat162 v2 = {h0, h1}; w = *(uint32_t*)&v2; }
                    else w = pack_bf2(f0 - __bfloat162float(h0),
                                      f1 - __bfloat162float(h1));
                    *(uint32_t*)&g_fe[grow] = w;
                }
                {
                    float ga = sX[tok * 65 + 32 + j];
                    float gb = sX[tok * 65 + 32 + j + 1];
                    __nv_bfloat16 h0 = __float2bfloat16(ga);
                    __nv_bfloat16 h1 = __float2bfloat16(gb);
                    uint32_t w;
                    if (c0 < 32) { __nv_bfloat162 v2 = {h0, h1}; w = *(uint32_t*)&v2; }
                    else w = pack_bf2(ga - __bfloat162float(h0),
                                      gb - __bfloat162float(h1));
                    *(uint32_t*)&g_ge[grow] = w;
                }
            }
        } else {
            for (int idx = t; idx < 4096; idx += 256) {
                int c = idx >> 6, tok = idx & 63;
                float v = sX[tok * 65 + c];
                g_ht[(size_t)(bb * 256 + (cc - 1) * 64 + c) * 4096 + tokBase + tok] =
                    __float2bfloat16(v);
            }
        }
    }
    __syncthreads();
    if (t == 0) g_g2blk[blockIdx.x] = fmaxf(sGm[0], sGm[1]);
}

// ---------------------------------------------------------------------------
// Attention kernel: persistent, 32 q/tile, 3 CTAs/SM target
// ---------------------------------------------------------------------------
#define HS_STRIDE 144
#define PB_STRIDE 144
#define FE_STRIDE 144
#define HS_OFF 0                      // 256*144 = 36864
#define PB_OFF 36864                  // 32*144  = 4608
#define FE_OFF 41472                  // 32*144  = 4608
#define GE_OFF 46080                  // 2*64*144 = 18432
#define GE_BUF 9216
#define SLP_OFF 64512                 // 4*32*4 = 512
#define SR_OFF 65024                  // 32
#define SGM_OFF 65056                 // 16
#define SNX_OFF 65072                 // 4
#define SM_BYTES 65088

__device__ __forceinline__ uint32_t smem_u32(const void* p) {
    uint32_t a;
    asm("{ .reg .u64 t; cvta.to.shared.u64 t, %1; cvt.u32.u64 %0, t; }"
        : "=r"(a) : "l"(p));
    return a;
}
__device__ __forceinline__ void cp_async16(uint32_t dst, const void* src) {
    asm volatile("cp.async.cg.shared.global [%0], [%1], 16;"
                 :: "r"(dst), "l"(src) : "memory");
}
__device__ __forceinline__ void mma16816(float* d, const uint32_t* a,
                                         const uint32_t* bv) {
    asm volatile(
        "mma.sync.aligned.m16n8k16.row.col.f32.bf16.bf16.f32 "
        "{%0,%1,%2,%3}, {%4,%5,%6,%7}, {%8,%9}, {%0,%1,%2,%3};"
        : "+f"(d[0]), "+f"(d[1]), "+f"(d[2]), "+f"(d[3])
        : "r"(a[0]), "r"(a[1]), "r"(a[2]), "r"(a[3]), "r"(bv[0]), "r"(bv[1]));
}
#define LDMX4(r0, r1, r2, r3, addr) \
    asm volatile("ldmatrix.sync.aligned.m8n8.x4.shared.b16 {%0,%1,%2,%3}, [%4];" \
                 : "=r"(r0), "=r"(r1), "=r"(r2), "=r"(r3) : "r"(addr))
#define CP_COMMIT() asm volatile("cp.async.commit_group;" ::: "memory")
#define CP_WAIT0()  asm volatile("cp.async.wait_group 0;" ::: "memory")

__global__ __launch_bounds__(256, 3) void attn_kernel(
    const float* __restrict__ x,
    const float* __restrict__ gamma_p,
    float* __restrict__ out)
{
    extern __shared__ char sm[];
    const int t = threadIdx.x;
    const int lane = t & 31;
    const int wid = t >> 5;
    const int gid = lane >> 2;
    const int tig = lane & 3;
    const int qw = wid & 1;        // 16-query slab
    const int kwS = wid >> 1;      // S: 16-key slice (of 64-key tile)
    const int cslab = (wid >> 1) * 64;   // O: 64-channel quarter

    float* sLp  = (float*)(sm + SLP_OFF);
    float* sR   = (float*)(sm + SR_OFF);
    float* sGms = (float*)(sm + SGM_OFF);
    int*   sNx  = (int*)(sm + SNX_OFF);
    const uint32_t smbase = smem_u32(sm);

    const int r0 = qw * 16 + gid;
    const int r1 = r0 + 8;
    const float gamma = *gamma_p;

    // ---- once: per-batch gmax (warp w handles batch w&3) ----
    {
        float gv = fmaxf(g_g2blk[(wid & 3) * 64 + lane],
                         g_g2blk[(wid & 3) * 64 + 32 + lane]);
#pragma unroll
        for (int o = 16; o > 0; o >>= 1)
            gv = fmaxf(gv, __shfl_xor_sync(0xffffffffu, gv, o));
        if (lane == 0) sR[wid] = gv;
    }
    __syncthreads();
    if (t < 4) sGms[t] = sqrtf(fmaxf(sR[t], sR[t + 4]));
    // (visible after the first work-loop barrier)

    // lane-relative ldmatrix offsets
    const uint32_t aS_l  = (qw * 16 + (lane & 15)) * FE_STRIDE + ((lane >> 4) << 4);
    const uint32_t bS_l  = (kwS * 16 + (lane & 7)) * FE_STRIDE + ((lane >> 3) << 4);
    const uint32_t aO_l  = (qw * 16 + (lane & 15)) * PB_STRIDE + ((lane >> 4) << 4);
    const uint32_t bO_l  = (cslab + (lane & 7)) * HS_STRIDE + ((lane >> 3) << 4);

    for (;;) {
        __syncthreads();                    // prev epilogue done; smem reusable
        if (t == 0) *sNx = atomicAdd(&g_ctr, 1);
        __syncthreads();
        const int n = *sNx;
        if (n >= NWORK) break;
        const int b = n >> 7;
        const int qBase = (n & 127) * 32;

        // ---- prologue: FE + GE(0) ----
        {
            int row = t >> 3, ch = t & 7;
            cp_async16(smbase + FE_OFF + row * FE_STRIDE + ch * 16,
                       g_fe + (size_t)(b * 4096 + qBase + row) * 64 + ch * 8);
        }
#pragma unroll
        for (int it = 0; it < 2; it++) {
            int idx = t + it * 256;
            int row = idx >> 3, ch = idx & 7;
            cp_async16(smbase + GE_OFF + row * FE_STRIDE + ch * 16,
                       g_ge + (size_t)(b * 4096 + row) * 64 + ch * 8);
        }
        CP_COMMIT();

        const float gms = sGms[b];
        const float mh0 = sqrtf(g_fn2[b * 4096 + qBase + r0]) * gms;
        const float mh1 = sqrtf(g_fn2[b * 4096 + qBase + r1]) * gms;

        float acc[8][4];
#pragma unroll
        for (int nj = 0; nj < 8; nj++)
#pragma unroll
            for (int q = 0; q < 4; q++) acc[nj][q] = 0.f;
        float rsum0 = 0.f, rsum1 = 0.f;

        CP_WAIT0();
        __syncthreads();

        for (int kt = 0; kt < 64; kt++) {
            // (top of tile: O(kt-1) done via bottom barrier of prev iter)
            // cp HS(kt) [256c x 64k] + GE(kt+1)
#pragma unroll
            for (int it = 0; it < 8; it++) {
                int idx = t + it * 256;
                int ch = idx >> 3, part = idx & 7;
                cp_async16(smbase + HS_OFF + ch * HS_STRIDE + part * 16,
                           g_ht + (size_t)(b * 256 + ch) * 4096 + kt * 64 + part * 8);
            }
            if (kt < 63) {
#pragma unroll
                for (int it = 0; it < 2; it++) {
                    int idx = t + it * 256;
                    int row = idx >> 3, ch = idx & 7;
                    cp_async16(smbase + GE_OFF + ((kt + 1) & 1) * GE_BUF +
                                   row * FE_STRIDE + ch * 16,
                               g_ge + (size_t)(b * 4096 + (kt + 1) * 64 + row) * 64 + ch * 8);
                }
            }
            CP_COMMIT();

            // ---- S-MMA: m16 n16, 3 split terms ----
            const uint32_t aS = smbase + FE_OFF + aS_l;
            const uint32_t bS = smbase + GE_OFF + (kt & 1) * GE_BUF + bS_l;
            uint32_t ahi[8], alo[8], bhi[8], blo[8];
            LDMX4(ahi[0], ahi[1], ahi[2], ahi[3], aS);
            LDMX4(ahi[4], ahi[5], ahi[6], ahi[7], aS + 32);
            LDMX4(alo[0], alo[1], alo[2], alo[3], aS + 64);
            LDMX4(alo[4], alo[5], alo[6], alo[7], aS + 96);
            LDMX4(bhi[0], bhi[1], bhi[2], bhi[3], bS);            // n8 blk0, k32 hi
            LDMX4(bhi[4], bhi[5], bhi[6], bhi[7], bS + 8 * FE_STRIDE);
            LDMX4(blo[0], blo[1], blo[2], blo[3], bS + 64);
            LDMX4(blo[4], blo[5], blo[6], blo[7], bS + 8 * FE_STRIDE + 64);

            float sacc[2][4];
#pragma unroll
            for (int nb = 0; nb < 2; nb++) {
#pragma unroll
                for (int q = 0; q < 4; q++) sacc[nb][q] = 0.f;
                mma16816(sacc[nb], &ahi[0], &bhi[nb * 4]);       // hi.hi k0:16
                mma16816(sacc[nb], &ahi[4], &bhi[nb * 4 + 2]);   // hi.hi k16:32
                mma16816(sacc[nb], &ahi[0], &blo[nb * 4]);       // hi.lo
                mma16816(sacc[nb], &ahi[4], &blo[nb * 4 + 2]);
                mma16816(sacc[nb], &alo[0], &bhi[nb * 4]);       // lo.hi
                mma16816(sacc[nb], &alo[4], &bhi[nb * 4 + 2]);
            }

            // ---- P = exp(S - mhat), PB store, row sums ----
            {
                float rs0 = 0.f, rs1 = 0.f;
#pragma unroll
                for (int nb = 0; nb < 2; nb++) {
                    float p0 = __expf(sacc[nb][0] - mh0);
                    float p1 = __expf(sacc[nb][1] - mh0);
                    float p2 = __expf(sacc[nb][2] - mh1);
                    float p3 = __expf(sacc[nb][3] - mh1);
                    rs0 += p0 + p1;
                    rs1 += p2 + p3;
                    int key = kwS * 16 + nb * 8 + tig * 2;
                    *(uint32_t*)(sm + PB_OFF + r0 * PB_STRIDE + key * 2) = pack_bf2(p0, p1);
                    *(uint32_t*)(sm + PB_OFF + r1 * PB_STRIDE + key * 2) = pack_bf2(p2, p3);
                }
                rs0 += __shfl_xor_sync(0xffffffffu, rs0, 1);
                rs0 += __shfl_xor_sync(0xffffffffu, rs0, 2);
                rs1 += __shfl_xor_sync(0xffffffffu, rs1, 1);
                rs1 += __shfl_xor_sync(0xffffffffu, rs1, 2);
                rsum0 += rs0;
                rsum1 += rs1;
            }

            CP_WAIT0();
            __syncthreads();   // HS(kt), GE(kt+1), PB(kt) visible

            // ---- O-MMA: A = P[16q x 64k], B = H[64c x 64k] ----
            {
                const uint32_t aO = smbase + PB_OFF + aO_l;
                const uint32_t bO = smbase + HS_OFF + bO_l;
                uint32_t af[16];
                LDMX4(af[0],  af[1],  af[2],  af[3],  aO);
                LDMX4(af[4],  af[5],  af[6],  af[7],  aO + 32);
                LDMX4(af[8],  af[9],  af[10], af[11], aO + 64);
                LDMX4(af[12], af[13], af[14], af[15], aO + 96);
#pragma unroll
                for (int nj = 0; nj < 8; nj++) {
                    uint32_t bf[8];
                    LDMX4(bf[0], bf[1], bf[2], bf[3], bO + nj * 8 * HS_STRIDE);
                    LDMX4(bf[4], bf[5], bf[6], bf[7], bO + nj * 8 * HS_STRIDE + 64);
                    mma16816(acc[nj], &af[0],  &bf[0]);
                    mma16816(acc[nj], &af[4],  &bf[2]);
                    mma16816(acc[nj], &af[8],  &bf[4]);
                    mma16816(acc[nj], &af[12], &bf[6]);
                }
            }
            __syncthreads();   // O done before HS/PB overwritten next iter
        }

        // ---- row sums ----
        if (tig == 0) {
            sLp[kwS * 32 + r0] = rsum0;
            sLp[kwS * 32 + r1] = rsum1;
        }
        __syncthreads();

        // ---- epilogue ----
        const float gl0 = gamma / (sLp[r0] + sLp[32 + r0] + sLp[64 + r0] + sLp[96 + r0]);
        const float gl1 = gamma / (sLp[r1] + sLp[32 + r1] + sLp[64 + r1] + sLp[96 + r1]);
        const size_t gb0 = (size_t)(b * NTOK + qBase + r0) * CDIM + cslab + tig * 2;
        const size_t gb1 = (size_t)(b * NTOK + qBase + r1) * CDIM + cslab + tig * 2;
#pragma unroll
        for (int nj = 0; nj < 8; nj++) {
            float2 xv0 = *(const float2*)&x[gb0 + nj * 8];
            float2 xv1 = *(const float2*)&x[gb1 + nj * 8];
            float2 o0, o1;
            o0.x = xv0.x + gl0 * acc[nj][0];
            o0.y = xv0.y + gl0 * acc[nj][1];
            o1.x = xv1.x + gl1 * acc[nj][2];
            o1.y = xv1.y + gl1 * acc[nj][3];
            *(float2*)&out[gb0 + nj * 8] = o0;
            *(float2*)&out[gb1 + nj * 8] = o1;
        }
    }
}

// ---------------------------------------------------------------------------
extern "C" void kernel_launch(void* const* d_in, const int* in_sizes, int n_in,
                              void* d_out, int out_size)
{
    const float* x  = (const float*)d_in[0];
    const float* wf = (const float*)d_in[1];
    const float* wg = (const float*)d_in[2];
    const float* wh = (const float*)d_in[3];
    const float* gm = (const float*)d_in[4];
    float* out = (float*)d_out;

    cudaFuncSetAttribute(attn_kernel,
                         cudaFuncAttributeMaxDynamicSharedMemorySize,
                         SM_BYTES);

    proj_kernel<<<256, 256>>>(x, wf, wg, wh);
    attn_kernel<<<444, 256, SM_BYTES>>>(x, gm, out);
}

// round 11
// speedup vs baseline: 1.1383x; 1.1353x over previous
#include <cuda_runtime.h>
#include <cuda_bf16.h>
#include <cstdint>

// ---------------------------------------------------------------------------
// ScaleSelfAttention: out = x + gamma * softmax((xWf)(xWg)^T) (xWh)
// B=4, N=4096, C=256, d=32
//  proj_kernel: h bf16 transposed [b][c][tok]; f,g as bf16 hi/lo split
//               extended operands (K=96): f_ext=[hi|hi|lo], g_ext=[hi|lo|hi].
//  attn_kernel: 64 q/CTA (grid 256), 64-key tiles. S via mma.sync bf16 (K=96),
//               warp = (16q, 32k). P = exp(S - mhat), mhat = ||f||*max||g||
//               (upper bound -> single pass, no rescale).
//               O += P.H: warp owns unique 32-channel slab (no H fragment
//               duplication), A = P over all 64 q. acc[4][4][4] = 64 regs.
// ---------------------------------------------------------------------------

#define BATCH 4
#define NTOK  4096
#define CDIM  256
#define DDIM  32

__device__ __nv_bfloat16 g_fe[BATCH * NTOK * 96];
__device__ __nv_bfloat16 g_ge[BATCH * NTOK * 96];
__device__ __nv_bfloat16 g_ht[BATCH * CDIM * NTOK];
__device__ float         g_fn2[BATCH * NTOK];
__device__ float         g_g2blk[256];

typedef unsigned long long ull;

__device__ __forceinline__ void fma2(ull& d, ull a, ull b) {
    asm("fma.rn.f32x2 %0, %1, %2, %0;" : "+l"(d) : "l"(a), "l"(b));
}
__device__ __forceinline__ ull splat2(float v) {
    ull r;
    asm("mov.b64 %0, {%1, %1};" : "=l"(r) : "f"(v));
    return r;
}
__device__ __forceinline__ float2 unpack2(ull v) {
    float2 r;
    asm("mov.b64 {%0, %1}, %2;" : "=f"(r.x), "=f"(r.y) : "l"(v));
    return r;
}
__device__ __forceinline__ uint32_t pack_bf2(float a, float b) {
    __nv_bfloat162 v = __floats2bfloat162_rn(a, b);
    return *(uint32_t*)&v;
}

// ---------------------------------------------------------------------------
// Projections (unchanged from R7)
// ---------------------------------------------------------------------------
__global__ __launch_bounds__(256) void proj_kernel(
    const float* __restrict__ x,
    const float* __restrict__ wf,
    const float* __restrict__ wg,
    const float* __restrict__ wh)
{
    __shared__ float sX[64 * 65];
    __shared__ float sW[64 * 64];
    __shared__ float sGm[2];

    const int t = threadIdx.x;
    const int rowBase = blockIdx.x * 64;
    const int bb = rowBase >> 12;
    const int tokBase = rowBase & 4095;
    const int rg = t >> 4;
    const int cg = t & 15;

    ull acc[5][8];
#pragma unroll
    for (int cc = 0; cc < 5; cc++)
#pragma unroll
        for (int q = 0; q < 8; q++) acc[cc][q] = 0ull;

    for (int kc = 0; kc < 4; kc++) {
        __syncthreads();
        for (int idx = t; idx < 4096; idx += 256) {
            int r = idx >> 6, kk = idx & 63;
            sX[r * 65 + kk] = x[(rowBase + r) * 256 + kc * 64 + kk];
        }
#pragma unroll
        for (int cc = 0; cc < 5; cc++) {
            __syncthreads();
            for (int idx = t; idx < 4096; idx += 256) {
                int kk = idx >> 6, j = idx & 63;
                int kglob = kc * 64 + kk;
                int c = cc * 64 + j;
                float w;
                if (c < 32)       w = wf[kglob * 32 + c];
                else if (c < 64)  w = wg[kglob * 32 + (c - 32)];
                else              w = wh[kglob * 256 + (c - 64)];
                sW[kk * 64 + j] = w;
            }
            __syncthreads();
#pragma unroll 4
            for (int kk = 0; kk < 64; kk++) {
                ulonglong2 bp = *(const ulonglong2*)&sW[kk * 64 + cg * 4];
                ull as[4];
#pragma unroll
                for (int i = 0; i < 4; i++)
                    as[i] = splat2(sX[(rg * 4 + i) * 65 + kk]);
#pragma unroll
                for (int i = 0; i < 4; i++) {
                    fma2(acc[cc][i * 2 + 0], as[i], bp.x);
                    fma2(acc[cc][i * 2 + 1], as[i], bp.y);
                }
            }
        }
    }

#pragma unroll
    for (int cc = 0; cc < 5; cc++) {
        __syncthreads();
#pragma unroll
        for (int i = 0; i < 4; i++) {
            float2 lo = unpack2(acc[cc][i * 2 + 0]);
            float2 hi = unpack2(acc[cc][i * 2 + 1]);
            sX[(rg * 4 + i) * 65 + cg * 4 + 0] = lo.x;
            sX[(rg * 4 + i) * 65 + cg * 4 + 1] = lo.y;
            sX[(rg * 4 + i) * 65 + cg * 4 + 2] = hi.x;
            sX[(rg * 4 + i) * 65 + cg * 4 + 3] = hi.y;
        }
        __syncthreads();

        if (cc == 0) {
            float g2 = 0.f;
            if (t < 64) {
                float f2 = 0.f;
#pragma unroll 8
                for (int k = 0; k < 32; k++) {
                    float v = sX[t * 65 + k];      f2 += v * v;
                    float w = sX[t * 65 + 32 + k]; g2 += w * w;
                }
                g_fn2[rowBase + t] = f2;
#pragma unroll
                for (int o = 16; o > 0; o >>= 1)
                    g2 = fmaxf(g2, __shfl_xor_sync(0xffffffffu, g2, o));
                if ((t & 31) == 0) sGm[t >> 5] = g2;
            }
            for (int idx = t; idx < 64 * 48; idx += 256) {
                int tok = idx / 48;
                int c0 = (idx % 48) * 2;
                size_t grow = (size_t)(bb * 4096 + tokBase + tok) * 96 + c0;
                {
                    int jf = (c0 < 64) ? (c0 & 31) : (c0 - 64);
                    float f0 = sX[tok * 65 + jf];
                    float f1 = sX[tok * 65 + jf + 1];
                    __nv_bfloat16 h0 = __float2bfloat16(f0);
                    __nv_bfloat16 h1 = __float2bfloat16(f1);
                    uint32_t w;
                    if (c0 < 64) {
                        __nv_bfloat162 v2 = {h0, h1};
                        w = *(uint32_t*)&v2;
                    } else {
                        w = pack_bf2(f0 - __bfloat162float(h0),
                                     f1 - __bfloat162float(h1));
                    }
                    *(uint32_t*)&g_fe[grow] = w;
                }
                {
                    int jg = (c0 < 32) ? c0 : ((c0 < 64) ? (c0 - 32) : (c0 - 64));
                    float ga = sX[tok * 65 + 32 + jg];
                    float gb = sX[tok * 65 + 32 + jg + 1];
                    __nv_bfloat16 h0 = __float2bfloat16(ga);
                    __nv_bfloat16 h1 = __float2bfloat16(gb);
                    uint32_t w;
                    if (c0 < 32 || c0 >= 64) {
                        __nv_bfloat162 v2 = {h0, h1};
                        w = *(uint32_t*)&v2;
                    } else {
                        w = pack_bf2(ga - __bfloat162float(h0),
                                     gb - __bfloat162float(h1));
                    }
                    *(uint32_t*)&g_ge[grow] = w;
                }
            }
        } else {
            for (int idx = t; idx < 4096; idx += 256) {
                int c = idx >> 6, tok = idx & 63;
                float v = sX[tok * 65 + c];
                g_ht[(size_t)(bb * 256 + (cc - 1) * 64 + c) * 4096 + tokBase + tok] =
                    __float2bfloat16(v);
            }
        }
    }
    __syncthreads();
    if (t == 0) g_g2blk[blockIdx.x] = fmaxf(sGm[0], sGm[1]);
}

// ---------------------------------------------------------------------------
// Attention kernel
// ---------------------------------------------------------------------------
#define HS_STRIDE 176
#define PB_STRIDE 176
#define FE_STRIDE 208
#define HS_OFF 0
#define PB_OFF (256 * HS_STRIDE)          // 45056
#define FE_OFF (PB_OFF + 64 * PB_STRIDE)  // 56320
#define GE_OFF (FE_OFF + 64 * FE_STRIDE)  // 69632
#define GE_BUF (64 * FE_STRIDE)           // 13312
#define SLP_OFF (GE_OFF + 2 * GE_BUF)     // 96256
#define SR_OFF (SLP_OFF + 512)            // 96768
#define SM_BYTES (SR_OFF + 32)            // 96800

__device__ __forceinline__ uint32_t smem_u32(const void* p) {
    uint32_t a;
    asm("{ .reg .u64 t; cvta.to.shared.u64 t, %1; cvt.u32.u64 %0, t; }"
        : "=r"(a) : "l"(p));
    return a;
}
__device__ __forceinline__ void cp_async16(uint32_t dst, const void* src) {
    asm volatile("cp.async.cg.shared.global [%0], [%1], 16;"
                 :: "r"(dst), "l"(src) : "memory");
}
__device__ __forceinline__ void mma16816(float* d, const uint32_t* a,
                                         const uint32_t* bv) {
    asm volatile(
        "mma.sync.aligned.m16n8k16.row.col.f32.bf16.bf16.f32 "
        "{%0,%1,%2,%3}, {%4,%5,%6,%7}, {%8,%9}, {%0,%1,%2,%3};"
        : "+f"(d[0]), "+f"(d[1]), "+f"(d[2]), "+f"(d[3])
        : "r"(a[0]), "r"(a[1]), "r"(a[2]), "r"(a[3]), "r"(bv[0]), "r"(bv[1]));
}
#define LDMX4(r0, r1, r2, r3, addr) \
    asm volatile("ldmatrix.sync.aligned.m8n8.x4.shared.b16 {%0,%1,%2,%3}, [%4];" \
                 : "=r"(r0), "=r"(r1), "=r"(r2), "=r"(r3) : "r"(addr))

__global__ __launch_bounds__(256, 2) void attn_kernel(
    const float* __restrict__ x,
    const float* __restrict__ gamma_p,
    float* __restrict__ out)
{
    extern __shared__ char sm[];
    const int t = threadIdx.x;
    const int lane = t & 31;
    const int wid = t >> 5;
    const int gid = lane >> 2;
    const int tig = lane & 3;
    const int b = blockIdx.y;
    const int qBase = blockIdx.x * 64;
    const int qw = wid & 3;       // S: 16-query slab
    const int kw = wid >> 2;      // S: 32-key half
    const int qoff = qw * 16;
    const int cslab = wid * 32;   // O: unique 32-channel slab

    float* sLp = (float*)(sm + SLP_OFF);   // [2][64] partial row sums
    float* sR  = (float*)(sm + SR_OFF);
    const uint32_t smbase = smem_u32(sm);

    const int r0 = qoff + gid;    // S rows
    const int r1 = r0 + 8;

    // ---- prologue: F_ext (once) + G_ext tile 0 ----
    for (int i = t; i < 768; i += 256) {
        int row = i / 12, ch = i % 12;
        cp_async16(smbase + FE_OFF + row * FE_STRIDE + ch * 16,
                   g_fe + (size_t)(b * 4096 + qBase + row) * 96 + ch * 8);
        cp_async16(smbase + GE_OFF + row * FE_STRIDE + ch * 16,
                   g_ge + (size_t)(b * 4096 + row) * 96 + ch * 8);
    }
    asm volatile("cp.async.commit_group;" ::: "memory");

    {
        float gv = g_g2blk[b * 64 + (t & 63)];
#pragma unroll
        for (int o = 16; o > 0; o >>= 1)
            gv = fmaxf(gv, __shfl_xor_sync(0xffffffffu, gv, o));
        if (lane == 0) sR[wid] = gv;
    }
    asm volatile("cp.async.wait_group 0;" ::: "memory");
    __syncthreads();

    float gm2 = sR[0];
#pragma unroll
    for (int w = 1; w < 8; w++) gm2 = fmaxf(gm2, sR[w]);
    const float gms = sqrtf(gm2);
    const float mh0 = sqrtf(g_fn2[b * 4096 + qBase + r0]) * gms;
    const float mh1 = sqrtf(g_fn2[b * 4096 + qBase + r1]) * gms;

    float acc[4][4][4];   // [qb][nb][frag]
#pragma unroll
    for (int qb = 0; qb < 4; qb++)
#pragma unroll
        for (int nj = 0; nj < 4; nj++)
#pragma unroll
            for (int q = 0; q < 4; q++) acc[qb][nj][q] = 0.f;

    float rsum0 = 0.f, rsum1 = 0.f;

    // ldmatrix lane addresses
    const uint32_t aS = smbase + FE_OFF + (qoff + (lane & 15)) * FE_STRIDE +
                        ((lane >> 4) << 4);
    const uint32_t bSb = smbase + GE_OFF + (kw * 32 + (lane & 7)) * FE_STRIDE +
                         ((lane >> 3) << 4);
    const uint32_t aO = smbase + PB_OFF + (lane & 15) * PB_STRIDE +
                        ((lane >> 4) << 4);
    const uint32_t bO = smbase + HS_OFF + (cslab + (lane & 7)) * HS_STRIDE +
                        ((lane >> 3) << 4);

    for (int kt = 0; kt < 64; kt++) {
        __syncthreads();   // prev O-MMA done with HS/PB

        // async: H tile (kt) + G_ext tile (kt+1)
#pragma unroll
        for (int it = 0; it < 8; it++) {
            int idx = t + it * 256;
            int ch = idx >> 3, part = idx & 7;
            cp_async16(smbase + HS_OFF + ch * HS_STRIDE + part * 16,
                       g_ht + (size_t)(b * 256 + ch) * 4096 + kt * 64 + part * 8);
        }
        if (kt < 63) {
#pragma unroll
            for (int it = 0; it < 3; it++) {
                int i = t + it * 256;
                int row = i / 12, ch = i % 12;
                cp_async16(smbase + GE_OFF + (((kt + 1) & 1) ? GE_BUF : 0) +
                               row * FE_STRIDE + ch * 16,
                           g_ge + (size_t)(b * 4096 + (kt + 1) * 64 + row) * 96 + ch * 8);
            }
        }
        asm volatile("cp.async.commit_group;" ::: "memory");

        // ---- S-MMA: m16 x n32 x k96 per warp ----
        const uint32_t bS = bSb + ((kt & 1) ? GE_BUF : 0);
        float sacc[4][4];
#pragma unroll
        for (int nb = 0; nb < 4; nb++)
#pragma unroll
            for (int q = 0; q < 4; q++) sacc[nb][q] = 0.f;

#pragma unroll
        for (int cp = 0; cp < 3; cp++) {       // three k32 chunks
            uint32_t af[8];
            LDMX4(af[0], af[1], af[2], af[3], aS + cp * 64);
            LDMX4(af[4], af[5], af[6], af[7], aS + cp * 64 + 32);
#pragma unroll
            for (int nb = 0; nb < 4; nb++) {
                uint32_t bf[4];
                LDMX4(bf[0], bf[1], bf[2], bf[3],
                      bS + nb * 8 * FE_STRIDE + cp * 64);
                mma16816(sacc[nb], &af[0], &bf[0]);
                mma16816(sacc[nb], &af[4], &bf[2]);
            }
        }

        // ---- P = exp(S - mhat), store bf16, row-sum accumulate ----
        float rs0 = 0.f, rs1 = 0.f;
#pragma unroll
        for (int nb = 0; nb < 4; nb++) {
            float p0 = __expf(sacc[nb][0] - mh0);
            float p1 = __expf(sacc[nb][1] - mh0);
            float p2 = __expf(sacc[nb][2] - mh1);
            float p3 = __expf(sacc[nb][3] - mh1);
            rs0 += p0 + p1;
            rs1 += p2 + p3;
            int col = kw * 32 + nb * 8 + tig * 2;
            *(uint32_t*)(sm + PB_OFF + r0 * PB_STRIDE + col * 2) = pack_bf2(p0, p1);
            *(uint32_t*)(sm + PB_OFF + r1 * PB_STRIDE + col * 2) = pack_bf2(p2, p3);
        }
        rs0 += __shfl_xor_sync(0xffffffffu, rs0, 1);
        rs0 += __shfl_xor_sync(0xffffffffu, rs0, 2);
        rs1 += __shfl_xor_sync(0xffffffffu, rs1, 1);
        rs1 += __shfl_xor_sync(0xffffffffu, rs1, 2);
        rsum0 += rs0;
        rsum1 += rs1;

        asm volatile("cp.async.wait_group 0;" ::: "memory");
        __syncthreads();   // P + H (+ next G) visible

        // ---- O-MMA: A = P[64q x 64k] (shared), B = H[32c slab] (unique) ----
#pragma unroll
        for (int kc = 0; kc < 2; kc++) {       // two k32 chunks
            uint32_t a[4][8];
#pragma unroll
            for (int qb = 0; qb < 4; qb++) {
                LDMX4(a[qb][0], a[qb][1], a[qb][2], a[qb][3],
                      aO + qb * 16 * PB_STRIDE + kc * 64);
                LDMX4(a[qb][4], a[qb][5], a[qb][6], a[qb][7],
                      aO + qb * 16 * PB_STRIDE + kc * 64 + 32);
            }
#pragma unroll
            for (int nb = 0; nb < 4; nb++) {
                uint32_t bf[4];
                LDMX4(bf[0], bf[1], bf[2], bf[3],
                      bO + nb * 8 * HS_STRIDE + kc * 64);
#pragma unroll
                for (int qb = 0; qb < 4; qb++) {
                    mma16816(acc[qb][nb], &a[qb][0], &bf[0]);
                    mma16816(acc[qb][nb], &a[qb][4], &bf[2]);
                }
            }
        }
    }

    // ---- final row sums (two k-halves), then gamma/l per row ----
    if (tig == 0) {
        sLp[kw * 64 + r0] = rsum0;
        sLp[kw * 64 + r1] = rsum1;
    }
    __syncthreads();
    const float gamma = *gamma_p;
    if (t < 64) sLp[t] = gamma / (sLp[t] + sLp[64 + t]);
    __syncthreads();

    // ---- epilogue: out = x + (gamma/l) * O  (acc[qb][nb]: rows qb*16+gid) ----
#pragma unroll
    for (int qb = 0; qb < 4; qb++) {
        int row0 = qb * 16 + gid;
        float gl0 = sLp[row0];
        float gl1 = sLp[row0 + 8];
        size_t g0 = (size_t)(b * NTOK + qBase + row0) * CDIM + cslab + tig * 2;
        size_t g1 = g0 + 8 * CDIM;
#pragma unroll
        for (int nb = 0; nb < 4; nb++) {
            float2 xv0 = *(const float2*)&x[g0 + nb * 8];
            float2 xv1 = *(const float2*)&x[g1 + nb * 8];
            float2 o0, o1;
            o0.x = xv0.x + gl0 * acc[qb][nb][0];
            o0.y = xv0.y + gl0 * acc[qb][nb][1];
            o1.x = xv1.x + gl1 * acc[qb][nb][2];
            o1.y = xv1.y + gl1 * acc[qb][nb][3];
            *(float2*)&out[g0 + nb * 8] = o0;
            *(float2*)&out[g1 + nb * 8] = o1;
        }
    }
}

// ---------------------------------------------------------------------------
extern "C" void kernel_launch(void* const* d_in, const int* in_sizes, int n_in,
                              void* d_out, int out_size)
{
    const float* x  = (const float*)d_in[0];
    const float* wf = (const float*)d_in[1];
    const float* wg = (const float*)d_in[2];
    const float* wh = (const float*)d_in[3];
    const float* gm = (const float*)d_in[4];
    float* out = (float*)d_out;

    cudaFuncSetAttribute(attn_kernel,
                         cudaFuncAttributeMaxDynamicSharedMemorySize,
                         SM_BYTES);

    proj_kernel<<<256, 256>>>(x, wf, wg, wh);
    attn_kernel<<<dim3(64, 4), 256, SM_BYTES>>>(x, gm, out);
}

// round 12
// speedup vs baseline: 1.3648x; 1.1989x over previous
#include <cuda_runtime.h>
#include <cuda_bf16.h>
#include <cstdint>

// ---------------------------------------------------------------------------
// ScaleSelfAttention: out = x + gamma * softmax((xWf)(xWg)^T) (xWh)
// B=4, N=4096, C=256, d=32
//  wext_kernel: W_ext[320][768] bf16 = [W_hi | W_lo | W_hi]  (f|g|h cols)
//  proj_kernel: tensor-core GEMM x_ext . W_ext (3-term hi/lo split, fp32 acc),
//               then same epilogue as before: f,g bf16 hi/lo extended (K=96),
//               h bf16 transposed, ||f||^2, per-block max ||g||^2.
//  attn_kernel: unchanged from R11 (best attn: 197.5 us).
// ---------------------------------------------------------------------------

#define BATCH 4
#define NTOK  4096
#define CDIM  256
#define DDIM  32

__device__ __nv_bfloat16 g_fe[BATCH * NTOK * 96];
__device__ __nv_bfloat16 g_ge[BATCH * NTOK * 96];
__device__ __nv_bfloat16 g_ht[BATCH * CDIM * NTOK];
__device__ __nv_bfloat16 g_we[320 * 768];
__device__ float         g_fn2[BATCH * NTOK];
__device__ float         g_g2blk[256];

__device__ __forceinline__ uint32_t pack_bf2(float a, float b) {
    __nv_bfloat162 v = __floats2bfloat162_rn(a, b);
    return *(uint32_t*)&v;
}
__device__ __forceinline__ uint32_t smem_u32(const void* p) {
    uint32_t a;
    asm("{ .reg .u64 t; cvta.to.shared.u64 t, %1; cvt.u32.u64 %0, t; }"
        : "=r"(a) : "l"(p));
    return a;
}
__device__ __forceinline__ void cp_async16(uint32_t dst, const void* src) {
    asm volatile("cp.async.cg.shared.global [%0], [%1], 16;"
                 :: "r"(dst), "l"(src) : "memory");
}
__device__ __forceinline__ void mma16816(float* d, const uint32_t* a,
                                         const uint32_t* bv) {
    asm volatile(
        "mma.sync.aligned.m16n8k16.row.col.f32.bf16.bf16.f32 "
        "{%0,%1,%2,%3}, {%4,%5,%6,%7}, {%8,%9}, {%0,%1,%2,%3};"
        : "+f"(d[0]), "+f"(d[1]), "+f"(d[2]), "+f"(d[3])
        : "r"(a[0]), "r"(a[1]), "r"(a[2]), "r"(a[3]), "r"(bv[0]), "r"(bv[1]));
}
#define LDMX4(r0, r1, r2, r3, addr) \
    asm volatile("ldmatrix.sync.aligned.m8n8.x4.shared.b16 {%0,%1,%2,%3}, [%4];" \
                 : "=r"(r0), "=r"(r1), "=r"(r2), "=r"(r3) : "r"(addr))
#define CP_COMMIT() asm volatile("cp.async.commit_group;" ::: "memory")
#define CP_WAIT1()  asm volatile("cp.async.wait_group 1;" ::: "memory")
#define CP_WAIT0()  asm volatile("cp.async.wait_group 0;" ::: "memory")

// ---------------------------------------------------------------------------
// W_ext precompute: g_we[n][0:256]=hi, [256:512]=lo, [512:768]=hi
// ---------------------------------------------------------------------------
__global__ __launch_bounds__(256) void wext_kernel(
    const float* __restrict__ wf,
    const float* __restrict__ wg,
    const float* __restrict__ wh)
{
    const int n = blockIdx.x;     // 0..319
    const int k = threadIdx.x;    // 0..255
    float w;
    if (n < 32)       w = wf[k * 32 + n];
    else if (n < 64)  w = wg[k * 32 + (n - 32)];
    else              w = wh[k * 256 + (n - 64)];
    __nv_bfloat16 hi = __float2bfloat16(w);
    __nv_bfloat16 lo = __float2bfloat16(w - __bfloat162float(hi));
    g_we[n * 768 + k]       = hi;
    g_we[n * 768 + 256 + k] = lo;
    g_we[n * 768 + 512 + k] = hi;
}

// ---------------------------------------------------------------------------
// Tensor-core projection kernel
// ---------------------------------------------------------------------------
#define XE_STRIDE 1040               // 65*16B: ldmatrix conflict-free
#define XE_OFF 0                     // 64*1040 = 66560
#define WB_OFF 66560                 // 2 x 64*272 = 34816
#define WB_BUF 17408
#define WT_STRIDE 272                // 17*16B
#define SG_OFF WB_OFF                // fp32 staging aliases W buffers
#define SG_STRIDE 66                 // floats (even -> aligned float2)
#define PGM_OFF (WB_OFF + 2 * WB_BUF)   // 101376
#define PSM_BYTES (PGM_OFF + 16)

__global__ __launch_bounds__(256, 2) void proj_kernel(
    const float* __restrict__ x)
{
    extern __shared__ char sm[];
    const int t = threadIdx.x;
    const int lane = t & 31;
    const int wid = t >> 5;
    const int gid = lane >> 2;
    const int tig = lane & 3;
    const int ts = wid & 3;          // 16-token slab
    const int nh = wid >> 2;         // 32-n half
    const int rowBase = blockIdx.x * 64;
    const int bb = rowBase >> 12;
    const int tokBase = rowBase & 4095;

    float* SG  = (float*)(sm + SG_OFF);
    float* sGm = (float*)(sm + PGM_OFF);
    const uint32_t smbase = smem_u32(sm);

    // ---- load x [64 tok x 256], split hi/lo into XE ----
    {
        const float4* xsrc = (const float4*)(x + (size_t)rowBase * 256);
        for (int i = t; i < 4096; i += 256) {
            int tok = i >> 6, c4 = i & 63;
            float4 v = xsrc[i];
            __nv_bfloat16 hx = __float2bfloat16(v.x);
            __nv_bfloat16 hy = __float2bfloat16(v.y);
            __nv_bfloat16 hz = __float2bfloat16(v.z);
            __nv_bfloat16 hw = __float2bfloat16(v.w);
            __nv_bfloat162 h01 = {hx, hy};
            __nv_bfloat162 h23 = {hz, hw};
            uint2 hi = {*(uint32_t*)&h01, *(uint32_t*)&h23};
            uint2 lo;
            lo.x = pack_bf2(v.x - __bfloat162float(hx), v.y - __bfloat162float(hy));
            lo.y = pack_bf2(v.z - __bfloat162float(hz), v.w - __bfloat162float(hw));
            char* xrow = sm + XE_OFF + tok * XE_STRIDE;
            *(uint2*)(xrow + c4 * 8) = hi;
            *(uint2*)(xrow + 512 + c4 * 8) = lo;
        }
    }

    // ---- A offsets per k-chunk: hi0,hi1,hi0,hi1,lo0,lo1 (bytes) ----
    const uint32_t AOFF[6] = {0u, 256u, 0u, 256u, 512u, 768u};

    // first W tile (nc=0, kc=0) -> buf 0
    for (int i = t; i < 1024; i += 256) {
        int row = i >> 4, seg = i & 15;
        cp_async16(smbase + WB_OFF + row * WT_STRIDE + seg * 16,
                   g_we + (size_t)row * 768 + seg * 8);
    }
    CP_COMMIT();

    const uint32_t aBase = smbase + XE_OFF +
        (ts * 16 + (lane & 15)) * XE_STRIDE + ((lane >> 4) << 4);
    const uint32_t bBase = smbase + WB_OFF +
        (nh * 32 + (lane & 7)) * WT_STRIDE + ((lane >> 3) << 4);

    for (int nc = 0; nc < 5; nc++) {
        float acc[4][4];
#pragma unroll
        for (int nb = 0; nb < 4; nb++)
#pragma unroll
            for (int q = 0; q < 4; q++) acc[nb][q] = 0.f;

        for (int kc = 0; kc < 6; kc++) {
            __syncthreads();      // readers of other buf / SG done
            if (kc < 5) {
                int buf = (kc + 1) & 1;
                for (int i = t; i < 1024; i += 256) {
                    int row = i >> 4, seg = i & 15;
                    cp_async16(smbase + WB_OFF + buf * WB_BUF +
                                   row * WT_STRIDE + seg * 16,
                               g_we + (size_t)(nc * 64 + row) * 768 +
                                   (kc + 1) * 128 + seg * 8);
                }
            }
            CP_COMMIT();
            CP_WAIT1();           // tile kc landed
            __syncthreads();      // visible to all warps

            // ---- compute on buf kc&1 ----
            const uint32_t aA = aBase + AOFF[kc];
            const uint32_t wB = bBase + (kc & 1) * WB_BUF;
            uint32_t af[8][4];
#pragma unroll
            for (int j = 0; j < 8; j++)
                LDMX4(af[j][0], af[j][1], af[j][2], af[j][3], aA + j * 32);
#pragma unroll
            for (int nb = 0; nb < 4; nb++) {
#pragma unroll
                for (int j32 = 0; j32 < 4; j32++) {
                    uint32_t bf[4];
                    LDMX4(bf[0], bf[1], bf[2], bf[3],
                          wB + nb * 8 * WT_STRIDE + j32 * 64);
                    mma16816(acc[nb], af[j32 * 2],     &bf[0]);
                    mma16816(acc[nb], af[j32 * 2 + 1], &bf[2]);
                }
            }
        }

        __syncthreads();          // all reads of W bufs done -> stage into SG
#pragma unroll
        for (int nb = 0; nb < 4; nb++) {
            int col = nh * 32 + nb * 8 + tig * 2;
            *(float2*)&SG[(ts * 16 + gid) * SG_STRIDE + col] =
                make_float2(acc[nb][0], acc[nb][1]);
            *(float2*)&SG[(ts * 16 + gid + 8) * SG_STRIDE + col] =
                make_float2(acc[nb][2], acc[nb][3]);
        }
        __syncthreads();

        // ---- epilogue for this 64-col chunk (cc == nc) ----
        if (nc == 0) {
            float g2 = 0.f;
            if (t < 64) {
                float f2 = 0.f;
#pragma unroll 8
                for (int k = 0; k < 32; k++) {
                    float v = SG[t * SG_STRIDE + k];      f2 += v * v;
                    float w = SG[t * SG_STRIDE + 32 + k]; g2 += w * w;
                }
                g_fn2[rowBase + t] = f2;
#pragma unroll
                for (int o = 16; o > 0; o >>= 1)
                    g2 = fmaxf(g2, __shfl_xor_sync(0xffffffffu, g2, o));
                if ((t & 31) == 0) sGm[t >> 5] = g2;
            }
            for (int idx = t; idx < 64 * 48; idx += 256) {
                int tok = idx / 48;
                int c0 = (idx % 48) * 2;
                size_t grow = (size_t)(bb * 4096 + tokBase + tok) * 96 + c0;
                {
                    int jf = (c0 < 64) ? (c0 & 31) : (c0 - 64);
                    float f0 = SG[tok * SG_STRIDE + jf];
                    float f1 = SG[tok * SG_STRIDE + jf + 1];
                    __nv_bfloat16 h0 = __float2bfloat16(f0);
                    __nv_bfloat16 h1 = __float2bfloat16(f1);
                    uint32_t w;
                    if (c0 < 64) {
                        __nv_bfloat162 v2 = {h0, h1};
                        w = *(uint32_t*)&v2;
                    } else {
                        w = pack_bf2(f0 - __bfloat162float(h0),
                                     f1 - __bfloat162float(h1));
                    }
                    *(uint32_t*)&g_fe[grow] = w;
                }
                {
                    int jg = (c0 < 32) ? c0 : ((c0 < 64) ? (c0 - 32) : (c0 - 64));
                    float ga = SG[tok * SG_STRIDE + 32 + jg];
                    float gb = SG[tok * SG_STRIDE + 32 + jg + 1];
                    __nv_bfloat16 h0 = __float2bfloat16(ga);
                    __nv_bfloat16 h1 = __float2bfloat16(gb);
                    uint32_t w;
                    if (c0 < 32 || c0 >= 64) {
                        __nv_bfloat162 v2 = {h0, h1};
                        w = *(uint32_t*)&v2;
                    } else {
                        w = pack_bf2(ga - __bfloat162float(h0),
                                     gb - __bfloat162float(h1));
                    }
                    *(uint32_t*)&g_ge[grow] = w;
                }
            }
        } else {
            for (int idx = t; idx < 4096; idx += 256) {
                int c = idx >> 6, tok = idx & 63;
                float v = SG[tok * SG_STRIDE + c];
                g_ht[(size_t)(bb * 256 + (nc - 1) * 64 + c) * 4096 + tokBase + tok] =
                    __float2bfloat16(v);
            }
        }

        // next n-chunk's first W tile -> buf 0 (after epilogue reads of SG)
        if (nc < 4) {
            __syncthreads();
            for (int i = t; i < 1024; i += 256) {
                int row = i >> 4, seg = i & 15;
                cp_async16(smbase + WB_OFF + row * WT_STRIDE + seg * 16,
                           g_we + (size_t)((nc + 1) * 64 + row) * 768 + seg * 8);
            }
            CP_COMMIT();
        }
    }
    __syncthreads();
    if (t == 0) g_g2blk[blockIdx.x] = fmaxf(sGm[0], sGm[1]);
}

// ---------------------------------------------------------------------------
// Attention kernel (unchanged from R11)
// ---------------------------------------------------------------------------
#define HS_STRIDE 176
#define PB_STRIDE 176
#define FE_STRIDE 208
#define HS_OFF 0
#define PB_OFF (256 * HS_STRIDE)
#define FE_OFF (PB_OFF + 64 * PB_STRIDE)
#define GE_OFF (FE_OFF + 64 * FE_STRIDE)
#define GE_BUF (64 * FE_STRIDE)
#define SLP_OFF (GE_OFF + 2 * GE_BUF)
#define SR_OFF (SLP_OFF + 512)
#define SM_BYTES (SR_OFF + 32)

__global__ __launch_bounds__(256, 2) void attn_kernel(
    const float* __restrict__ x,
    const float* __restrict__ gamma_p,
    float* __restrict__ out)
{
    extern __shared__ char sm[];
    const int t = threadIdx.x;
    const int lane = t & 31;
    const int wid = t >> 5;
    const int gid = lane >> 2;
    const int tig = lane & 3;
    const int b = blockIdx.y;
    const int qBase = blockIdx.x * 64;
    const int qw = wid & 3;
    const int kw = wid >> 2;
    const int qoff = qw * 16;
    const int cslab = wid * 32;

    float* sLp = (float*)(sm + SLP_OFF);
    float* sR  = (float*)(sm + SR_OFF);
    const uint32_t smbase = smem_u32(sm);

    const int r0 = qoff + gid;
    const int r1 = r0 + 8;

    for (int i = t; i < 768; i += 256) {
        int row = i / 12, ch = i % 12;
        cp_async16(smbase + FE_OFF + row * FE_STRIDE + ch * 16,
                   g_fe + (size_t)(b * 4096 + qBase + row) * 96 + ch * 8);
        cp_async16(smbase + GE_OFF + row * FE_STRIDE + ch * 16,
                   g_ge + (size_t)(b * 4096 + row) * 96 + ch * 8);
    }
    CP_COMMIT();

    {
        float gv = g_g2blk[b * 64 + (t & 63)];
#pragma unroll
        for (int o = 16; o > 0; o >>= 1)
            gv = fmaxf(gv, __shfl_xor_sync(0xffffffffu, gv, o));
        if (lane == 0) sR[wid] = gv;
    }
    CP_WAIT0();
    __syncthreads();

    float gm2 = sR[0];
#pragma unroll
    for (int w = 1; w < 8; w++) gm2 = fmaxf(gm2, sR[w]);
    const float gms = sqrtf(gm2);
    const float mh0 = sqrtf(g_fn2[b * 4096 + qBase + r0]) * gms;
    const float mh1 = sqrtf(g_fn2[b * 4096 + qBase + r1]) * gms;

    float acc[4][4][4];
#pragma unroll
    for (int qb = 0; qb < 4; qb++)
#pragma unroll
        for (int nj = 0; nj < 4; nj++)
#pragma unroll
            for (int q = 0; q < 4; q++) acc[qb][nj][q] = 0.f;

    float rsum0 = 0.f, rsum1 = 0.f;

    const uint32_t aS = smbase + FE_OFF + (qoff + (lane & 15)) * FE_STRIDE +
                        ((lane >> 4) << 4);
    const uint32_t bSb = smbase + GE_OFF + (kw * 32 + (lane & 7)) * FE_STRIDE +
                         ((lane >> 3) << 4);
    const uint32_t aO = smbase + PB_OFF + (lane & 15) * PB_STRIDE +
                        ((lane >> 4) << 4);
    const uint32_t bO = smbase + HS_OFF + (cslab + (lane & 7)) * HS_STRIDE +
                        ((lane >> 3) << 4);

    for (int kt = 0; kt < 64; kt++) {
        __syncthreads();

#pragma unroll
        for (int it = 0; it < 8; it++) {
            int idx = t + it * 256;
            int ch = idx >> 3, part = idx & 7;
            cp_async16(smbase + HS_OFF + ch * HS_STRIDE + part * 16,
                       g_ht + (size_t)(b * 256 + ch) * 4096 + kt * 64 + part * 8);
        }
        if (kt < 63) {
#pragma unroll
            for (int it = 0; it < 3; it++) {
                int i = t + it * 256;
                int row = i / 12, ch = i % 12;
                cp_async16(smbase + GE_OFF + (((kt + 1) & 1) ? GE_BUF : 0) +
                               row * FE_STRIDE + ch * 16,
                           g_ge + (size_t)(b * 4096 + (kt + 1) * 64 + row) * 96 + ch * 8);
            }
        }
        CP_COMMIT();

        const uint32_t bS = bSb + ((kt & 1) ? GE_BUF : 0);
        float sacc[4][4];
#pragma unroll
        for (int nb = 0; nb < 4; nb++)
#pragma unroll
            for (int q = 0; q < 4; q++) sacc[nb][q] = 0.f;

#pragma unroll
        for (int cp = 0; cp < 3; cp++) {
            uint32_t af[8];
            LDMX4(af[0], af[1], af[2], af[3], aS + cp * 64);
            LDMX4(af[4], af[5], af[6], af[7], aS + cp * 64 + 32);
#pragma unroll
            for (int nb = 0; nb < 4; nb++) {
                uint32_t bf[4];
                LDMX4(bf[0], bf[1], bf[2], bf[3],
                      bS + nb * 8 * FE_STRIDE + cp * 64);
                mma16816(sacc[nb], &af[0], &bf[0]);
                mma16816(sacc[nb], &af[4], &bf[2]);
            }
        }

        float rs0 = 0.f, rs1 = 0.f;
#pragma unroll
        for (int nb = 0; nb < 4; nb++) {
            float p0 = __expf(sacc[nb][0] - mh0);
            float p1 = __expf(sacc[nb][1] - mh0);
            float p2 = __expf(sacc[nb][2] - mh1);
            float p3 = __expf(sacc[nb][3] - mh1);
            rs0 += p0 + p1;
            rs1 += p2 + p3;
            int col = kw * 32 + nb * 8 + tig * 2;
            *(uint32_t*)(sm + PB_OFF + r0 * PB_STRIDE + col * 2) = pack_bf2(p0, p1);
            *(uint32_t*)(sm + PB_OFF + r1 * PB_STRIDE + col * 2) = pack_bf2(p2, p3);
        }
        rs0 += __shfl_xor_sync(0xffffffffu, rs0, 1);
        rs0 += __shfl_xor_sync(0xffffffffu, rs0, 2);
        rs1 += __shfl_xor_sync(0xffffffffu, rs1, 1);
        rs1 += __shfl_xor_sync(0xffffffffu, rs1, 2);
        rsum0 += rs0;
        rsum1 += rs1;

        CP_WAIT0();
        __syncthreads();

#pragma unroll
        for (int kc = 0; kc < 2; kc++) {
            uint32_t a[4][8];
#pragma unroll
            for (int qb = 0; qb < 4; qb++) {
                LDMX4(a[qb][0], a[qb][1], a[qb][2], a[qb][3],
                      aO + qb * 16 * PB_STRIDE + kc * 64);
                LDMX4(a[qb][4], a[qb][5], a[qb][6], a[qb][7],
                      aO + qb * 16 * PB_STRIDE + kc * 64 + 32);
            }
#pragma unroll
            for (int nb = 0; nb < 4; nb++) {
                uint32_t bf[4];
                LDMX4(bf[0], bf[1], bf[2], bf[3],
                      bO + nb * 8 * HS_STRIDE + kc * 64);
#pragma unroll
                for (int qb = 0; qb < 4; qb++) {
                    mma16816(acc[qb][nb], &a[qb][0], &bf[0]);
                    mma16816(acc[qb][nb], &a[qb][4], &bf[2]);
                }
            }
        }
    }

    if (tig == 0) {
        sLp[kw * 64 + r0] = rsum0;
        sLp[kw * 64 + r1] = rsum1;
    }
    __syncthreads();
    const float gamma = *gamma_p;
    if (t < 64) sLp[t] = gamma / (sLp[t] + sLp[64 + t]);
    __syncthreads();

#pragma unroll
    for (int qb = 0; qb < 4; qb++) {
        int row0 = qb * 16 + gid;
        float gl0 = sLp[row0];
        float gl1 = sLp[row0 + 8];
        size_t g0 = (size_t)(b * NTOK + qBase + row0) * CDIM + cslab + tig * 2;
        size_t g1 = g0 + 8 * CDIM;
#pragma unroll
        for (int nb = 0; nb < 4; nb++) {
            float2 xv0 = *(const float2*)&x[g0 + nb * 8];
            float2 xv1 = *(const float2*)&x[g1 + nb * 8];
            float2 o0, o1;
            o0.x = xv0.x + gl0 * acc[qb][nb][0];
            o0.y = xv0.y + gl0 * acc[qb][nb][1];
            o1.x = xv1.x + gl1 * acc[qb][nb][2];
            o1.y = xv1.y + gl1 * acc[qb][nb][3];
            *(float2*)&out[g0 + nb * 8] = o0;
            *(float2*)&out[g1 + nb * 8] = o1;
        }
    }
}

// ---------------------------------------------------------------------------
extern "C" void kernel_launch(void* const* d_in, const int* in_sizes, int n_in,
                              void* d_out, int out_size)
{
    const float* x  = (const float*)d_in[0];
    const float* wf = (const float*)d_in[1];
    const float* wg = (const float*)d_in[2];
    const float* wh = (const float*)d_in[3];
    const float* gm = (const float*)d_in[4];
    float* out = (float*)d_out;

    cudaFuncSetAttribute(proj_kernel,
                         cudaFuncAttributeMaxDynamicSharedMemorySize,
                         PSM_BYTES);
    cudaFuncSetAttribute(attn_kernel,
                         cudaFuncAttributeMaxDynamicSharedMemorySize,
                         SM_BYTES);

    wext_kernel<<<320, 256>>>(wf, wg, wh);
    proj_kernel<<<256, 256, PSM_BYTES>>>(x);
    attn_kernel<<<dim3(64, 4), 256, SM_BYTES>>>(x, gm, out);
}

// round 13
// speedup vs baseline: 1.3650x; 1.0001x over previous
#include <cuda_runtime.h>
#include <cuda_bf16.h>
#include <cstdint>

// ---------------------------------------------------------------------------
// ScaleSelfAttention: out = x + gamma * softmax((xWf)(xWg)^T) (xWh)
// B=4, N=4096, C=256, d=32
//  wext_kernel: W_ext[320][768] bf16 = [W_hi | W_lo | W_hi]  (f|g|h cols)
//  proj_kernel: tensor-core GEMM x_ext . W_ext (3-term hi/lo split, fp32 acc),
//               then same epilogue as before: f,g bf16 hi/lo extended (K=96),
//               h bf16 transposed, ||f||^2, per-block max ||g||^2.
//  attn_kernel: unchanged from R11 (best attn: 197.5 us).
// ---------------------------------------------------------------------------

#define BATCH 4
#define NTOK  4096
#define CDIM  256
#define DDIM  32

__device__ __nv_bfloat16 g_fe[BATCH * NTOK * 96];
__device__ __nv_bfloat16 g_ge[BATCH * NTOK * 96];
__device__ __nv_bfloat16 g_ht[BATCH * CDIM * NTOK];
__device__ __nv_bfloat16 g_we[320 * 768];
__device__ float         g_fn2[BATCH * NTOK];
__device__ float         g_g2blk[256];

__device__ __forceinline__ uint32_t pack_bf2(float a, float b) {
    __nv_bfloat162 v = __floats2bfloat162_rn(a, b);
    return *(uint32_t*)&v;
}
__device__ __forceinline__ uint32_t smem_u32(const void* p) {
    uint32_t a;
    asm("{ .reg .u64 t; cvta.to.shared.u64 t, %1; cvt.u32.u64 %0, t; }"
        : "=r"(a) : "l"(p));
    return a;
}
__device__ __forceinline__ void cp_async16(uint32_t dst, const void* src) {
    asm volatile("cp.async.cg.shared.global [%0], [%1], 16;"
                 :: "r"(dst), "l"(src) : "memory");
}
__device__ __forceinline__ void mma16816(float* d, const uint32_t* a,
                                         const uint32_t* bv) {
    asm volatile(
        "mma.sync.aligned.m16n8k16.row.col.f32.bf16.bf16.f32 "
        "{%0,%1,%2,%3}, {%4,%5,%6,%7}, {%8,%9}, {%0,%1,%2,%3};"
        : "+f"(d[0]), "+f"(d[1]), "+f"(d[2]), "+f"(d[3])
        : "r"(a[0]), "r"(a[1]), "r"(a[2]), "r"(a[3]), "r"(bv[0]), "r"(bv[1]));
}
#define LDMX4(r0, r1, r2, r3, addr) \
    asm volatile("ldmatrix.sync.aligned.m8n8.x4.shared.b16 {%0,%1,%2,%3}, [%4];" \
                 : "=r"(r0), "=r"(r1), "=r"(r2), "=r"(r3) : "r"(addr))
#define CP_COMMIT() asm volatile("cp.async.commit_group;" ::: "memory")
#define CP_WAIT1()  asm volatile("cp.async.wait_group 1;" ::: "memory")
#define CP_WAIT0()  asm volatile("cp.async.wait_group 0;" ::: "memory")

// ---------------------------------------------------------------------------
// W_ext precompute: g_we[n][0:256]=hi, [256:512]=lo, [512:768]=hi
// ---------------------------------------------------------------------------
__global__ __launch_bounds__(256) void wext_kernel(
    const float* __restrict__ wf,
    const float* __restrict__ wg,
    const float* __restrict__ wh)
{
    const int n = blockIdx.x;     // 0..319
    const int k = threadIdx.x;    // 0..255
    float w;
    if (n < 32)       w = wf[k * 32 + n];
    else if (n < 64)  w = wg[k * 32 + (n - 32)];
    else              w = wh[k * 256 + (n - 64)];
    __nv_bfloat16 hi = __float2bfloat16(w);
    __nv_bfloat16 lo = __float2bfloat16(w - __bfloat162float(hi));
    g_we[n * 768 + k]       = hi;
    g_we[n * 768 + 256 + k] = lo;
    g_we[n * 768 + 512 + k] = hi;
}

// ---------------------------------------------------------------------------
// Tensor-core projection kernel
// ---------------------------------------------------------------------------
#define XE_STRIDE 1040               // 65*16B: ldmatrix conflict-free
#define XE_OFF 0                     // 64*1040 = 66560
#define WB_OFF 66560                 // 2 x 64*272 = 34816
#define WB_BUF 17408
#define WT_STRIDE 272                // 17*16B
#define SG_OFF WB_OFF                // fp32 staging aliases W buffers
#define SG_STRIDE 66                 // floats (even -> aligned float2)
#define PGM_OFF (WB_OFF + 2 * WB_BUF)   // 101376
#define PSM_BYTES (PGM_OFF + 16)

__global__ __launch_bounds__(256, 2) void proj_kernel(
    const float* __restrict__ x)
{
    extern __shared__ char sm[];
    const int t = threadIdx.x;
    const int lane = t & 31;
    const int wid = t >> 5;
    const int gid = lane >> 2;
    const int tig = lane & 3;
    const int ts = wid & 3;          // 16-token slab
    const int nh = wid >> 2;         // 32-n half
    const int rowBase = blockIdx.x * 64;
    const int bb = rowBase >> 12;
    const int tokBase = rowBase & 4095;

    float* SG  = (float*)(sm + SG_OFF);
    float* sGm = (float*)(sm + PGM_OFF);
    const uint32_t smbase = smem_u32(sm);

    // ---- load x [64 tok x 256], split hi/lo into XE ----
    {
        const float4* xsrc = (const float4*)(x + (size_t)rowBase * 256);
        for (int i = t; i < 4096; i += 256) {
            int tok = i >> 6, c4 = i & 63;
            float4 v = xsrc[i];
            __nv_bfloat16 hx = __float2bfloat16(v.x);
            __nv_bfloat16 hy = __float2bfloat16(v.y);
            __nv_bfloat16 hz = __float2bfloat16(v.z);
            __nv_bfloat16 hw = __float2bfloat16(v.w);
            __nv_bfloat162 h01 = {hx, hy};
            __nv_bfloat162 h23 = {hz, hw};
            uint2 hi = {*(uint32_t*)&h01, *(uint32_t*)&h23};
            uint2 lo;
            lo.x = pack_bf2(v.x - __bfloat162float(hx), v.y - __bfloat162float(hy));
            lo.y = pack_bf2(v.z - __bfloat162float(hz), v.w - __bfloat162float(hw));
            char* xrow = sm + XE_OFF + tok * XE_STRIDE;
            *(uint2*)(xrow + c4 * 8) = hi;
            *(uint2*)(xrow + 512 + c4 * 8) = lo;
        }
    }

    // ---- A offsets per k-chunk: hi0,hi1,hi0,hi1,lo0,lo1 (bytes) ----
    const uint32_t AOFF[6] = {0u, 256u, 0u, 256u, 512u, 768u};

    // first W tile (nc=0, kc=0) -> buf 0
    for (int i = t; i < 1024; i += 256) {
        int row = i >> 4, seg = i & 15;
        cp_async16(smbase + WB_OFF + row * WT_STRIDE + seg * 16,
                   g_we + (size_t)row * 768 + seg * 8);
    }
    CP_COMMIT();

    const uint32_t aBase = smbase + XE_OFF +
        (ts * 16 + (lane & 15)) * XE_STRIDE + ((lane >> 4) << 4);
    const uint32_t bBase = smbase + WB_OFF +
        (nh * 32 + (lane & 7)) * WT_STRIDE + ((lane >> 3) << 4);

    for (int nc = 0; nc < 5; nc++) {
        float acc[4][4];
#pragma unroll
        for (int nb = 0; nb < 4; nb++)
#pragma unroll
            for (int q = 0; q < 4; q++) acc[nb][q] = 0.f;

        for (int kc = 0; kc < 6; kc++) {
            __syncthreads();      // readers of other buf / SG done
            if (kc < 5) {
                int buf = (kc + 1) & 1;
                for (int i = t; i < 1024; i += 256) {
                    int row = i >> 4, seg = i & 15;
                    cp_async16(smbase + WB_OFF + buf * WB_BUF +
                                   row * WT_STRIDE + seg * 16,
                               g_we + (size_t)(nc * 64 + row) * 768 +
                                   (kc + 1) * 128 + seg * 8);
                }
            }
            CP_COMMIT();
            CP_WAIT1();           // tile kc landed
            __syncthreads();      // visible to all warps

            // ---- compute on buf kc&1 ----
            const uint32_t aA = aBase + AOFF[kc];
            const uint32_t wB = bBase + (kc & 1) * WB_BUF;
            uint32_t af[8][4];
#pragma unroll
            for (int j = 0; j < 8; j++)
                LDMX4(af[j][0], af[j][1], af[j][2], af[j][3], aA + j * 32);
#pragma unroll
            for (int nb = 0; nb < 4; nb++) {
#pragma unroll
                for (int j32 = 0; j32 < 4; j32++) {
                    uint32_t bf[4];
                    LDMX4(bf[0], bf[1], bf[2], bf[3],
                          wB + nb * 8 * WT_STRIDE + j32 * 64);
                    mma16816(acc[nb], af[j32 * 2],     &bf[0]);
                    mma16816(acc[nb], af[j32 * 2 + 1], &bf[2]);
                }
            }
        }

        __syncthreads();          // all reads of W bufs done -> stage into SG
#pragma unroll
        for (int nb = 0; nb < 4; nb++) {
            int col = nh * 32 + nb * 8 + tig * 2;
            *(float2*)&SG[(ts * 16 + gid) * SG_STRIDE + col] =
                make_float2(acc[nb][0], acc[nb][1]);
            *(float2*)&SG[(ts * 16 + gid + 8) * SG_STRIDE + col] =
                make_float2(acc[nb][2], acc[nb][3]);
        }
        __syncthreads();

        // ---- epilogue for this 64-col chunk (cc == nc) ----
        if (nc == 0) {
            float g2 = 0.f;
            if (t < 64) {
                float f2 = 0.f;
#pragma unroll 8
                for (int k = 0; k < 32; k++) {
                    float v = SG[t * SG_STRIDE + k];      f2 += v * v;
                    float w = SG[t * SG_STRIDE + 32 + k]; g2 += w * w;
                }
                g_fn2[rowBase + t] = f2;
#pragma unroll
                for (int o = 16; o > 0; o >>= 1)
                    g2 = fmaxf(g2, __shfl_xor_sync(0xffffffffu, g2, o));
                if ((t & 31) == 0) sGm[t >> 5] = g2;
            }
            for (int idx = t; idx < 64 * 48; idx += 256) {
                int tok = idx / 48;
                int c0 = (idx % 48) * 2;
                size_t grow = (size_t)(bb * 4096 + tokBase + tok) * 96 + c0;
                {
                    int jf = (c0 < 64) ? (c0 & 31) : (c0 - 64);
                    float f0 = SG[tok * SG_STRIDE + jf];
                    float f1 = SG[tok * SG_STRIDE + jf + 1];
                    __nv_bfloat16 h0 = __float2bfloat16(f0);
                    __nv_bfloat16 h1 = __float2bfloat16(f1);
                    uint32_t w;
                    if (c0 < 64) {
                        __nv_bfloat162 v2 = {h0, h1};
                        w = *(uint32_t*)&v2;
                    } else {
                        w = pack_bf2(f0 - __bfloat162float(h0),
                                     f1 - __bfloat162float(h1));
                    }
                    *(uint32_t*)&g_fe[grow] = w;
                }
                {
                    int jg = (c0 < 32) ? c0 : ((c0 < 64) ? (c0 - 32) : (c0 - 64));
                    float ga = SG[tok * SG_STRIDE + 32 + jg];
                    float gb = SG[tok * SG_STRIDE + 32 + jg + 1];
                    __nv_bfloat16 h0 = __float2bfloat16(ga);
                    __nv_bfloat16 h1 = __float2bfloat16(gb);
                    uint32_t w;
                    if (c0 < 32 || c0 >= 64) {
                        __nv_bfloat162 v2 = {h0, h1};
                        w = *(uint32_t*)&v2;
                    } else {
                        w = pack_bf2(ga - __bfloat162float(h0),
                                     gb - __bfloat162float(h1));
                    }
                    *(uint32_t*)&g_ge[grow] = w;
                }
            }
        } else {
            for (int idx = t; idx < 4096; idx += 256) {
                int c = idx >> 6, tok = idx & 63;
                float v = SG[tok * SG_STRIDE + c];
                g_ht[(size_t)(bb * 256 + (nc - 1) * 64 + c) * 4096 + tokBase + tok] =
                    __float2bfloat16(v);
            }
        }

        // next n-chunk's first W tile -> buf 0 (after epilogue reads of SG)
        if (nc < 4) {
            __syncthreads();
            for (int i = t; i < 1024; i += 256) {
                int row = i >> 4, seg = i & 15;
                cp_async16(smbase + WB_OFF + row * WT_STRIDE + seg * 16,
                           g_we + (size_t)((nc + 1) * 64 + row) * 768 + seg * 8);
            }
            CP_COMMIT();
        }
    }
    __syncthreads();
    if (t == 0) g_g2blk[blockIdx.x] = fmaxf(sGm[0], sGm[1]);
}

// ---------------------------------------------------------------------------
// Attention kernel (unchanged from R11)
// ---------------------------------------------------------------------------
#define HS_STRIDE 176
#define PB_STRIDE 176
#define FE_STRIDE 208
#define HS_OFF 0
#define PB_OFF (256 * HS_STRIDE)
#define FE_OFF (PB_OFF + 64 * PB_STRIDE)
#define GE_OFF (FE_OFF + 64 * FE_STRIDE)
#define GE_BUF (64 * FE_STRIDE)
#define SLP_OFF (GE_OFF + 2 * GE_BUF)
#define SR_OFF (SLP_OFF + 512)
#define SM_BYTES (SR_OFF + 32)

__global__ __launch_bounds__(256, 2) void attn_kernel(
    const float* __restrict__ x,
    const float* __restrict__ gamma_p,
    float* __restrict__ out)
{
    extern __shared__ char sm[];
    const int t = threadIdx.x;
    const int lane = t & 31;
    const int wid = t >> 5;
    const int gid = lane >> 2;
    const int tig = lane & 3;
    const int b = blockIdx.y;
    const int qBase = blockIdx.x * 64;
    const int qw = wid & 3;
    const int kw = wid >> 2;
    const int qoff = qw * 16;
    const int cslab = wid * 32;

    float* sLp = (float*)(sm + SLP_OFF);
    float* sR  = (float*)(sm + SR_OFF);
    const uint32_t smbase = smem_u32(sm);

    const int r0 = qoff + gid;
    const int r1 = r0 + 8;

    for (int i = t; i < 768; i += 256) {
        int row = i / 12, ch = i % 12;
        cp_async16(smbase + FE_OFF + row * FE_STRIDE + ch * 16,
                   g_fe + (size_t)(b * 4096 + qBase + row) * 96 + ch * 8);
        cp_async16(smbase + GE_OFF + row * FE_STRIDE + ch * 16,
                   g_ge + (size_t)(b * 4096 + row) * 96 + ch * 8);
    }
    CP_COMMIT();

    {
        float gv = g_g2blk[b * 64 + (t & 63)];
#pragma unroll
        for (int o = 16; o > 0; o >>= 1)
            gv = fmaxf(gv, __shfl_xor_sync(0xffffffffu, gv, o));
        if (lane == 0) sR[wid] = gv;
    }
    CP_WAIT0();
    __syncthreads();

    float gm2 = sR[0];
#pragma unroll
    for (int w = 1; w < 8; w++) gm2 = fmaxf(gm2, sR[w]);
    const float gms = sqrtf(gm2);
    const float mh0 = sqrtf(g_fn2[b * 4096 + qBase + r0]) * gms;
    const float mh1 = sqrtf(g_fn2[b * 4096 + qBase + r1]) * gms;

    float acc[4][4][4];
#pragma unroll
    for (int qb = 0; qb < 4; qb++)
#pragma unroll
        for (int nj = 0; nj < 4; nj++)
#pragma unroll
            for (int q = 0; q < 4; q++) acc[qb][nj][q] = 0.f;

    float rsum0 = 0.f, rsum1 = 0.f;

    const uint32_t aS = smbase + FE_OFF + (qoff + (lane & 15)) * FE_STRIDE +
                        ((lane >> 4) << 4);
    const uint32_t bSb = smbase + GE_OFF + (kw * 32 + (lane & 7)) * FE_STRIDE +
                         ((lane >> 3) << 4);
    const uint32_t aO = smbase + PB_OFF + (lane & 15) * PB_STRIDE +
                        ((lane >> 4) << 4);
    const uint32_t bO = smbase + HS_OFF + (cslab + (lane & 7)) * HS_STRIDE +
                        ((lane >> 3) << 4);

    for (int kt = 0; kt < 64; kt++) {
        __syncthreads();

#pragma unroll
        for (int it = 0; it < 8; it++) {
            int idx = t + it * 256;
            int ch = idx >> 3, part = idx & 7;
            cp_async16(smbase + HS_OFF + ch * HS_STRIDE + part * 16,
                       g_ht + (size_t)(b * 256 + ch) * 4096 + kt * 64 + part * 8);
        }
        if (kt < 63) {
#pragma unroll
            for (int it = 0; it < 3; it++) {
                int i = t + it * 256;
                int row = i / 12, ch = i % 12;
                cp_async16(smbase + GE_OFF + (((kt + 1) & 1) ? GE_BUF : 0) +
                               row * FE_STRIDE + ch * 16,
                           g_ge + (size_t)(b * 4096 + (kt + 1) * 64 + row) * 96 + ch * 8);
            }
        }
        CP_COMMIT();

        const uint32_t bS = bSb + ((kt & 1) ? GE_BUF : 0);
        float sacc[4][4];
#pragma unroll
        for (int nb = 0; nb < 4; nb++)
#pragma unroll
            for (int q = 0; q < 4; q++) sacc[nb][q] = 0.f;

#pragma unroll
        for (int cp = 0; cp < 3; cp++) {
            uint32_t af[8];
            LDMX4(af[0], af[1], af[2], af[3], aS + cp * 64);
            LDMX4(af[4], af[5], af[6], af[7], aS + cp * 64 + 32);
#pragma unroll
            for (int nb = 0; nb < 4; nb++) {
                uint32_t bf[4];
                LDMX4(bf[0], bf[1], bf[2], bf[3],
                      bS + nb * 8 * FE_STRIDE + cp * 64);
                mma16816(sacc[nb], &af[0], &bf[0]);
                mma16816(sacc[nb], &af[4], &bf[2]);
            }
        }

        float rs0 = 0.f, rs1 = 0.f;
#pragma unroll
        for (int nb = 0; nb < 4; nb++) {
            float p0 = __expf(sacc[nb][0] - mh0);
            float p1 = __expf(sacc[nb][1] - mh0);
            float p2 = __expf(sacc[nb][2] - mh1);
            float p3 = __expf(sacc[nb][3] - mh1);
            rs0 += p0 + p1;
            rs1 += p2 + p3;
            int col = kw * 32 + nb * 8 + tig * 2;
            *(uint32_t*)(sm + PB_OFF + r0 * PB_STRIDE + col * 2) = pack_bf2(p0, p1);
            *(uint32_t*)(sm + PB_OFF + r1 * PB_STRIDE + col * 2) = pack_bf2(p2, p3);
        }
        rs0 += __shfl_xor_sync(0xffffffffu, rs0, 1);
        rs0 += __shfl_xor_sync(0xffffffffu, rs0, 2);
        rs1 += __shfl_xor_sync(0xffffffffu, rs1, 1);
        rs1 += __shfl_xor_sync(0xffffffffu, rs1, 2);
        rsum0 += rs0;
        rsum1 += rs1;

        CP_WAIT0();
        __syncthreads();

#pragma unroll
        for (int kc = 0; kc < 2; kc++) {
            uint32_t a[4][8];
#pragma unroll
            for (int qb = 0; qb < 4; qb++) {
                LDMX4(a[qb][0], a[qb][1], a[qb][2], a[qb][3],
                      aO + qb * 16 * PB_STRIDE + kc * 64);
                LDMX4(a[qb][4], a[qb][5], a[qb][6], a[qb][7],
                      aO + qb * 16 * PB_STRIDE + kc * 64 + 32);
            }
#pragma unroll
            for (int nb = 0; nb < 4; nb++) {
                uint32_t bf[4];
                LDMX4(bf[0], bf[1], bf[2], bf[3],
                      bO + nb * 8 * HS_STRIDE + kc * 64);
#pragma unroll
                for (int qb = 0; qb < 4; qb++) {
                    mma16816(acc[qb][nb], &a[qb][0], &bf[0]);
                    mma16816(acc[qb][nb], &a[qb][4], &bf[2]);
                }
            }
        }
    }

    if (tig == 0) {
        sLp[kw * 64 + r0] = rsum0;
        sLp[kw * 64 + r1] = rsum1;
    }
    __syncthreads();
    const float gamma = *gamma_p;
    if (t < 64) sLp[t] = gamma / (sLp[t] + sLp[64 + t]);
    __syncthreads();

#pragma unroll
    for (int qb = 0; qb < 4; qb++) {
        int row0 = qb * 16 + gid;
        float gl0 = sLp[row0];
        float gl1 = sLp[row0 + 8];
        size_t g0 = (size_t)(b * NTOK + qBase + row0) * CDIM + cslab + tig * 2;
        size_t g1 = g0 + 8 * CDIM;
#pragma unroll
        for (int nb = 0; nb < 4; nb++) {
            float2 xv0 = *(const float2*)&x[g0 + nb * 8];
            float2 xv1 = *(const float2*)&x[g1 + nb * 8];
            float2 o0, o1;
            o0.x = xv0.x + gl0 * acc[qb][nb][0];
            o0.y = xv0.y + gl0 * acc[qb][nb][1];
            o1.x = xv1.x + gl1 * acc[qb][nb][2];
            o1.y = xv1.y + gl1 * acc[qb][nb][3];
            *(float2*)&out[g0 + nb * 8] = o0;
            *(float2*)&out[g1 + nb * 8] = o1;
        }
    }
}

// ---------------------------------------------------------------------------
extern "C" void kernel_launch(void* const* d_in, const int* in_sizes, int n_in,
                              void* d_out, int out_size)
{
    const float* x  = (const float*)d_in[0];
    const float* wf = (const float*)d_in[1];
    const float* wg = (const float*)d_in[2];
    const float* wh = (const float*)d_in[3];
    const float* gm = (const float*)d_in[4];
    float* out = (float*)d_out;

    cudaFuncSetAttribute(proj_kernel,
                         cudaFuncAttributeMaxDynamicSharedMemorySize,
                         PSM_BYTES);
    cudaFuncSetAttribute(attn_kernel,
                         cudaFuncAttributeMaxDynamicSharedMemorySize,
                         SM_BYTES);

    wext_kernel<<<320, 256>>>(wf, wg, wh);
    proj_kernel<<<256, 256, PSM_BYTES>>>(x);
    attn_kernel<<<dim3(64, 4), 256, SM_BYTES>>>(x, gm, out);
}